// round 10
// baseline (speedup 1.0000x reference)
#include <cuda_runtime.h>
#include <cuda_fp16.h>
#include <cstdint>
#include <math.h>

// ---------------- problem constants ----------------
#define B_   4
#define S_   1024
#define HD   2048
#define NH   16
#define NKV  4
#define DH   128
#define T_   (B_*S_)        // 4096
#define KVD  (NKV*DH)       // 512
#define QKVN (HD + 2*KVD)   // 3072 packed q|k|v columns

// ---------------- scratch (device globals) ----------
__device__ float  g_ao  [(size_t)T_*HD];
__device__ float  g_bqkv[QKVN];
__device__ float2 g_rope[S_ * (DH/2)];              // [s][d/2] -> (cos, sin)
__device__ __half g_wqkv[(size_t)HD*QKVN];
__device__ __half g_woh[(size_t)HD*HD];
__device__ __half g_wgh[(size_t)HD*HD];
__device__ __half g_wuh[(size_t)HD*HD];
__device__ __half g_wdh[(size_t)HD*HD];
__device__ __half g_xnh[(size_t)T_*HD];
__device__ __half g_qkv[(size_t)T_*QKVN];
__device__ __half g_cxh[(size_t)T_*HD];
__device__ __half g_hh [(size_t)T_*HD];
__device__ __half g_gth[(size_t)T_*HD];
__device__ __half g_guh[(size_t)T_*HD];

// ---------------- ptx helpers -----------------------
__device__ __forceinline__ void cpa16(unsigned int dst, const void* src) {
    asm volatile("cp.async.cg.shared.global [%0], [%1], 16;\n" :: "r"(dst), "l"(src));
}
__device__ __forceinline__ void cpa_commit() {
    asm volatile("cp.async.commit_group;\n");
}
template<int N>
__device__ __forceinline__ void cpa_wait() {
    asm volatile("cp.async.wait_group %0;\n" :: "n"(N));
}
__device__ __forceinline__ void ldsm4(unsigned &r0, unsigned &r1, unsigned &r2, unsigned &r3,
                                      unsigned int addr) {
    asm volatile("ldmatrix.sync.aligned.m8n8.x4.shared.b16 {%0,%1,%2,%3}, [%4];\n"
                 : "=r"(r0), "=r"(r1), "=r"(r2), "=r"(r3) : "r"(addr));
}
__device__ __forceinline__ void ldsm4t(unsigned &r0, unsigned &r1, unsigned &r2, unsigned &r3,
                                       unsigned int addr) {
    asm volatile("ldmatrix.sync.aligned.m8n8.x4.trans.shared.b16 {%0,%1,%2,%3}, [%4];\n"
                 : "=r"(r0), "=r"(r1), "=r"(r2), "=r"(r3) : "r"(addr));
}
__device__ __forceinline__ void mma16816(float c[4], const unsigned a[4], const unsigned b[2]) {
    asm volatile(
        "mma.sync.aligned.m16n8k16.row.col.f32.f16.f16.f32 "
        "{%0,%1,%2,%3},{%4,%5,%6,%7},{%8,%9},{%0,%1,%2,%3};\n"
        : "+f"(c[0]), "+f"(c[1]), "+f"(c[2]), "+f"(c[3])
        : "r"(a[0]), "r"(a[1]), "r"(a[2]), "r"(a[3]), "r"(b[0]), "r"(b[1]));
}
__device__ __forceinline__ unsigned packh2(float a, float b) {
    __half2 h = __floats2half2_rn(a, b);
    return *reinterpret_cast<unsigned*>(&h);
}

// ---------------- fp16 GEMM, 128x128 tile, 4 warps @ 64x64, BK=64, 2-stage --
// OUTH: fp16 out. SILU: out = silu(gateH)*v, fp16 out. ROPE: rotary on
// column pairs with cn < HD+KVD using g_rope (QKV projection only).
template<bool OUTH, bool SILU, bool ROPE>
__global__ __launch_bounds__(128, 2)
void hgemm_k(const __half* __restrict__ A, const __half* __restrict__ B,
             float* __restrict__ Cf, __half* __restrict__ Ch,
             const float* __restrict__ bias, const float* __restrict__ resid,
             const __half* __restrict__ gateH,
             int M, int N, int K, int lda, int ldb, int ldc, int ldr,
             float scale) {
    constexpr int ASTG = 128 * 72;    // halves: 128 rows x 64 (+8 pad)
    constexpr int BSTG = 64 * 136;    // halves: 64 k-rows x 128 (+8 pad)
    extern __shared__ __half sm[];
    __half* sA = sm;
    __half* sB = sm + 2 * ASTG;

    const int tid = threadIdx.x, lane = tid & 31, warp = tid >> 5;
    const int warpM = warp >> 1, warpN = warp & 1;     // 2 x 2 warps, 64x64 each
    const int m0 = blockIdx.y * 128, n0 = blockIdx.x * 128;

    const unsigned suA = (unsigned)__cvta_generic_to_shared(sA);
    const unsigned suB = (unsigned)__cvta_generic_to_shared(sB);

    const int arow = tid >> 3, acc8 = (tid & 7) * 8;    // A: 16 rows per round
    const int brow = tid >> 4, bcc8 = (tid & 15) * 8;   // B: 8 k-rows per round

    auto load_stage = [&](int kt, int buf) {
        const int k0 = kt << 6;
        #pragma unroll
        for (int i = 0; i < 8; i++) {
            int row = arow + i * 16;
            cpa16(suA + (unsigned)(buf * ASTG + row * 72 + acc8) * 2,
                  A + (long long)(m0 + row) * lda + k0 + acc8);
        }
        #pragma unroll
        for (int i = 0; i < 8; i++) {
            int kr = brow + i * 8;
            cpa16(suB + (unsigned)(buf * BSTG + kr * 136 + bcc8) * 2,
                  B + (long long)(k0 + kr) * ldb + n0 + bcc8);
        }
    };

    float acc[4][8][4];
    #pragma unroll
    for (int i = 0; i < 4; i++)
        #pragma unroll
        for (int j = 0; j < 8; j++)
            #pragma unroll
            for (int q = 0; q < 4; q++) acc[i][j][q] = 0.f;

    const int ktiles = K >> 6;
    load_stage(0, 0); cpa_commit();
    if (ktiles > 1) load_stage(1, 1);
    cpa_commit();

    for (int kt = 0; kt < ktiles; kt++) {
        const int buf = kt & 1;
        cpa_wait<1>();
        __syncthreads();

        #pragma unroll
        for (int kk = 0; kk < 4; kk++) {
            unsigned af[4][4], bf[8][2];
            const int ar = warpM * 64 + (lane & 15);
            const int ac = kk * 16 + (lane >> 4) * 8;
            #pragma unroll
            for (int i = 0; i < 4; i++)
                ldsm4(af[i][0], af[i][1], af[i][2], af[i][3],
                      suA + (unsigned)(buf * ASTG + (ar + i * 16) * 72 + ac) * 2);

            const int kr = kk * 16 + (lane & 15);
            const int ncl = (lane >> 4) * 8;
            #pragma unroll
            for (int jj = 0; jj < 4; jj++) {
                const int nb = warpN * 64 + jj * 16;
                ldsm4t(bf[jj*2][0], bf[jj*2][1], bf[jj*2+1][0], bf[jj*2+1][1],
                       suB + (unsigned)(buf * BSTG + kr * 136 + nb + ncl) * 2);
            }
            #pragma unroll
            for (int i = 0; i < 4; i++)
                #pragma unroll
                for (int j = 0; j < 8; j++)
                    mma16816(acc[i][j], af[i], bf[j]);
        }

        __syncthreads();                       // protect buf before overwrite
        if (kt + 2 < ktiles) load_stage(kt + 2, buf);
        cpa_commit();
    }

    #pragma unroll
    for (int i = 0; i < 4; i++) {
        const int r = m0 + warpM * 64 + i * 16 + (lane >> 2);
        #pragma unroll
        for (int j = 0; j < 8; j++) {
            const int cn = n0 + warpN * 64 + j * 8 + (lane & 3) * 2;
            float b0 = 0.f, b1 = 0.f;
            if (bias) { b0 = bias[cn]; b1 = bias[cn + 1]; }
            float v0 = acc[i][j][0] * scale + b0;
            float v1 = acc[i][j][1] * scale + b1;
            float v2 = acc[i][j][2] * scale + b0;
            float v3 = acc[i][j][3] * scale + b1;
            if (ROPE) {
                if (cn < HD + KVD) {
                    const int pidx = (cn & (DH - 1)) >> 1;
                    const float2 t0 = g_rope[(r & (S_ - 1)) * (DH/2) + pidx];
                    const float2 t1 = g_rope[((r + 8) & (S_ - 1)) * (DH/2) + pidx];
                    float nv0 = t0.x * v0 - t0.y * v1;
                    float nv1 = t0.y * v0 + t0.x * v1;
                    float nv2 = t1.x * v2 - t1.y * v3;
                    float nv3 = t1.y * v2 + t1.x * v3;
                    v0 = nv0; v1 = nv1; v2 = nv2; v3 = nv3;
                }
            }
            if (SILU) {
                float2 ga = __half22float2(
                    *reinterpret_cast<const __half2*>(&gateH[(long long)r * ldr + cn]));
                float2 gb = __half22float2(
                    *reinterpret_cast<const __half2*>(&gateH[(long long)(r + 8) * ldr + cn]));
                v0 *= ga.x / (1.0f + __expf(-ga.x));
                v1 *= ga.y / (1.0f + __expf(-ga.y));
                v2 *= gb.x / (1.0f + __expf(-gb.x));
                v3 *= gb.y / (1.0f + __expf(-gb.y));
            } else if (resid) {
                const float* rr0 = &resid[(long long)r * ldr + cn];
                const float* rr1 = &resid[(long long)(r + 8) * ldr + cn];
                v0 += rr0[0]; v1 += rr0[1]; v2 += rr1[0]; v3 += rr1[1];
            }
            if (OUTH) {
                *reinterpret_cast<__half2*>(&Ch[(long long)r * ldc + cn]) =
                    __floats2half2_rn(v0, v1);
                *reinterpret_cast<__half2*>(&Ch[(long long)(r + 8) * ldc + cn]) =
                    __floats2half2_rn(v2, v3);
            } else {
                *reinterpret_cast<float2*>(&Cf[(long long)r * ldc + cn]) = make_float2(v0, v1);
                *reinterpret_cast<float2*>(&Cf[(long long)(r + 8) * ldc + cn]) = make_float2(v2, v3);
            }
        }
    }
}

// ---------------- FlashAttention-2 over packed qkv [T, 3072] ----------------
__global__ __launch_bounds__(256, 1)
void flash_k(const __half* __restrict__ qkv, const float* __restrict__ mask,
             __half* __restrict__ O) {
    extern __shared__ char smraw[];
    float* smask = (float*)smraw;
    const unsigned suKV = (unsigned)__cvta_generic_to_shared(smraw + 4096);

    const int tid = threadIdx.x, lane = tid & 31, warp = tid >> 5;
    const int s0 = blockIdx.x * 128;
    const int h = blockIdx.y, b = blockIdx.z;
    const int kvh = h / (NH / NKV);

    const __half* Qg = qkv + ((long long)(b * S_ + s0)) * QKVN + h * DH;
    const __half* Kg = qkv + ((long long)b * S_) * QKVN + HD + kvh * DH;
    const __half* Vg = qkv + ((long long)b * S_) * QKVN + HD + KVD + kvh * DH;

    for (int i = tid; i < S_ / 4; i += 256)
        *(float4*)&smask[i * 4] = *(const float4*)&mask[b * S_ + i * 4];

    #pragma unroll
    for (int i = 0; i < 8; i++) {
        int idx = tid + 256 * i;
        int row = idx >> 4, col = (idx & 15) * 8;
        cpa16(suKV + (unsigned)(row * 136 + col) * 2, Qg + (long long)row * QKVN + col);
    }
    cpa_commit();
    cpa_wait<0>();
    __syncthreads();

    unsigned af[8][4];
    {
        const int ar = warp * 16 + (lane & 15);
        const int ac = (lane >> 4) * 8;
        #pragma unroll
        for (int t = 0; t < 8; t++)
            ldsm4(af[t][0], af[t][1], af[t][2], af[t][3],
                  suKV + (unsigned)(ar * 136 + t * 16 + ac) * 2);
    }
    __syncthreads();

    auto load_kv = [&](int tile, int stage) {
        const int kv0 = tile * 64;
        const unsigned kb = suKV + (unsigned)(stage * 17408) * 2;
        const unsigned vbx = kb + 8704u * 2;
        #pragma unroll
        for (int i = 0; i < 4; i++) {
            int idx = tid + 256 * i;
            int row = idx >> 4, col = (idx & 15) * 8;
            cpa16(kb + (unsigned)(row * 136 + col) * 2,
                  Kg + (long long)(kv0 + row) * QKVN + col);
            cpa16(vbx + (unsigned)(row * 136 + col) * 2,
                  Vg + (long long)(kv0 + row) * QKVN + col);
        }
    };

    load_kv(0, 0); cpa_commit();
    load_kv(1, 1); cpa_commit();

    float oacc[16][4];
    #pragma unroll
    for (int d = 0; d < 16; d++)
        #pragma unroll
        for (int q = 0; q < 4; q++) oacc[d][q] = 0.f;

    float m0r = -INFINITY, m1r = -INFINITY, l0r = 0.f, l1r = 0.f;
    const int r0 = warp * 16 + (lane >> 2);
    const float mq0 = smask[s0 + r0];
    const float mq1 = smask[s0 + r0 + 8];
    const float scale = 0.08838834764831845f;

    for (int t = 0; t < 16; t++) {
        cpa_wait<1>();
        __syncthreads();
        const int stage = t & 1;
        const unsigned kb = suKV + (unsigned)(stage * 17408) * 2;
        const unsigned vbx = kb + 8704u * 2;

        float sacc[8][4];
        #pragma unroll
        for (int j = 0; j < 8; j++)
            #pragma unroll
            for (int q = 0; q < 4; q++) sacc[j][q] = 0.f;

        #pragma unroll
        for (int ks = 0; ks < 8; ks++) {
            unsigned bf[8][2];
            #pragma unroll
            for (int g = 0; g < 4; g++) {
                const int br = g * 16 + (lane >> 4) * 8 + (lane & 7);
                const int bc = ks * 16 + ((lane >> 3) & 1) * 8;
                ldsm4(bf[g*2][0], bf[g*2][1], bf[g*2+1][0], bf[g*2+1][1],
                      kb + (unsigned)(br * 136 + bc) * 2);
            }
            #pragma unroll
            for (int j = 0; j < 8; j++)
                mma16816(sacc[j], af[ks], bf[j]);
        }

        const int kvb = t * 64;
        float t0 = -INFINITY, t1 = -INFINITY;
        #pragma unroll
        for (int j = 0; j < 8; j++) {
            const int c = kvb + j * 8 + (lane & 3) * 2;
            const float mk0 = smask[c], mk1 = smask[c + 1];
            sacc[j][0] = (mq0 * mk0 == 0.f) ? -1e30f : sacc[j][0] * scale;
            sacc[j][1] = (mq0 * mk1 == 0.f) ? -1e30f : sacc[j][1] * scale;
            sacc[j][2] = (mq1 * mk0 == 0.f) ? -1e30f : sacc[j][2] * scale;
            sacc[j][3] = (mq1 * mk1 == 0.f) ? -1e30f : sacc[j][3] * scale;
            t0 = fmaxf(t0, fmaxf(sacc[j][0], sacc[j][1]));
            t1 = fmaxf(t1, fmaxf(sacc[j][2], sacc[j][3]));
        }
        t0 = fmaxf(t0, __shfl_xor_sync(0xffffffffu, t0, 1));
        t0 = fmaxf(t0, __shfl_xor_sync(0xffffffffu, t0, 2));
        t1 = fmaxf(t1, __shfl_xor_sync(0xffffffffu, t1, 1));
        t1 = fmaxf(t1, __shfl_xor_sync(0xffffffffu, t1, 2));

        const float mn0 = fmaxf(m0r, t0), mn1 = fmaxf(m1r, t1);
        const float a0 = __expf(m0r - mn0), a1 = __expf(m1r - mn1);
        m0r = mn0; m1r = mn1;

        float s0s = 0.f, s1s = 0.f;
        #pragma unroll
        for (int j = 0; j < 8; j++) {
            sacc[j][0] = __expf(sacc[j][0] - mn0);
            sacc[j][1] = __expf(sacc[j][1] - mn0);
            sacc[j][2] = __expf(sacc[j][2] - mn1);
            sacc[j][3] = __expf(sacc[j][3] - mn1);
            s0s += sacc[j][0] + sacc[j][1];
            s1s += sacc[j][2] + sacc[j][3];
        }
        s0s += __shfl_xor_sync(0xffffffffu, s0s, 1);
        s0s += __shfl_xor_sync(0xffffffffu, s0s, 2);
        s1s += __shfl_xor_sync(0xffffffffu, s1s, 1);
        s1s += __shfl_xor_sync(0xffffffffu, s1s, 2);
        l0r = l0r * a0 + s0s;
        l1r = l1r * a1 + s1s;

        #pragma unroll
        for (int d = 0; d < 16; d++) {
            oacc[d][0] *= a0; oacc[d][1] *= a0;
            oacc[d][2] *= a1; oacc[d][3] *= a1;
        }

        unsigned pa[4][4];
        #pragma unroll
        for (int kk = 0; kk < 4; kk++) {
            pa[kk][0] = packh2(sacc[2*kk][0],   sacc[2*kk][1]);
            pa[kk][1] = packh2(sacc[2*kk][2],   sacc[2*kk][3]);
            pa[kk][2] = packh2(sacc[2*kk+1][0], sacc[2*kk+1][1]);
            pa[kk][3] = packh2(sacc[2*kk+1][2], sacc[2*kk+1][3]);
        }

        #pragma unroll
        for (int kk = 0; kk < 4; kk++) {
            const int kr = kk * 16 + (lane & 15);
            const int ncl = (lane >> 4) * 8;
            unsigned vbf[16][2];
            #pragma unroll
            for (int dp = 0; dp < 8; dp++)
                ldsm4t(vbf[dp*2][0], vbf[dp*2][1], vbf[dp*2+1][0], vbf[dp*2+1][1],
                       vbx + (unsigned)(kr * 136 + dp * 16 + ncl) * 2);
            #pragma unroll
            for (int d = 0; d < 16; d++)
                mma16816(oacc[d], pa[kk], vbf[d]);
        }

        __syncthreads();
        if (t + 2 < 16) load_kv(t + 2, stage);
        cpa_commit();
    }

    const float i0 = 1.f / l0r, i1 = 1.f / l1r;
    __half* Og = O + ((long long)(b * S_ + s0 + r0)) * HD + h * DH;
    #pragma unroll
    for (int d = 0; d < 16; d++) {
        const int col = d * 8 + (lane & 3) * 2;
        *reinterpret_cast<__half2*>(&Og[col]) =
            __floats2half2_rn(oacc[d][0] * i0, oacc[d][1] * i0);
        *reinterpret_cast<__half2*>(&Og[(long long)8 * HD + col]) =
            __floats2half2_rn(oacc[d][2] * i1, oacc[d][3] * i1);
    }
}

// ---------------- elementwise kernels ---------------------------------------
__global__ void rope_tab_k() {
    int idx = blockIdx.x * blockDim.x + threadIdx.x;   // over S_ * DH/2
    if (idx >= S_ * (DH/2)) return;
    int s = idx >> 6, p = idx & 63;
    float inv = powf(10000.0f, -(float)(2 * p) / (float)DH);
    float ang = (float)s * inv;
    float sn, cs; sincosf(ang, &sn, &cs);
    g_rope[idx] = make_float2(cs, sn);
}

#define SEG_BIG  (HD*HD)      // 4M
#define SEG_SM   (HD*KVD)     // 1M
__global__ void f2h_all_k(const float* __restrict__ wq, const float* __restrict__ wk,
                          const float* __restrict__ wv, const float* __restrict__ wo,
                          const float* __restrict__ wg, const float* __restrict__ wu,
                          const float* __restrict__ wd,
                          __half* __restrict__ wqkv,
                          __half* __restrict__ oo, __half* __restrict__ og,
                          __half* __restrict__ ou, __half* __restrict__ od) {
    long long i = ((long long)blockIdx.x * blockDim.x + threadIdx.x) * 8;
    const long long big = SEG_BIG, sg = SEG_SM;
    const float* src; __half* dst; long long off, doff;
    if (i < big) {
        src = wq; off = i;
        doff = (off >> 11) * QKVN + (off & 2047);
        dst = wqkv;
    } else if (i < big + sg) {
        src = wk; off = i - big;
        doff = (off >> 9) * QKVN + HD + (off & 511);
        dst = wqkv;
    } else if (i < big + 2*sg) {
        src = wv; off = i - big - sg;
        doff = (off >> 9) * QKVN + HD + KVD + (off & 511);
        dst = wqkv;
    } else if (i < 2*big + 2*sg) { src = wo; off = i - big - 2*sg;  dst = oo; doff = off; }
    else if   (i < 3*big + 2*sg) { src = wg; off = i - 2*big - 2*sg; dst = og; doff = off; }
    else if   (i < 4*big + 2*sg) { src = wu; off = i - 3*big - 2*sg; dst = ou; doff = off; }
    else                         { src = wd; off = i - 4*big - 2*sg; dst = od; doff = off; }
    float4 v0 = *reinterpret_cast<const float4*>(&src[off]);
    float4 v1 = *reinterpret_cast<const float4*>(&src[off + 4]);
    uint4 u;
    u.x = packh2(v0.x, v0.y); u.y = packh2(v0.z, v0.w);
    u.z = packh2(v1.x, v1.y); u.w = packh2(v1.z, v1.w);
    *reinterpret_cast<uint4*>(&dst[doff]) = u;
}

__global__ void rmsnorm_h(const float* __restrict__ x, const float* __restrict__ g,
                          __half* __restrict__ o) {
    __shared__ float sh[256];
    int row = blockIdx.x;
    const float* xr = x + (long long)row * HD;
    float s = 0.f;
    for (int c = threadIdx.x; c < HD; c += 256) { float v = xr[c]; s += v * v; }
    sh[threadIdx.x] = s; __syncthreads();
    for (int st = 128; st > 0; st >>= 1) {
        if (threadIdx.x < st) sh[threadIdx.x] += sh[threadIdx.x + st];
        __syncthreads();
    }
    float inv = 1.0f / sqrtf(sh[0] / (float)HD + 1e-8f);
    __half* orow = o + (long long)row * HD;
    for (int c = threadIdx.x; c < HD; c += 256)
        orow[c] = __float2half(xr[c] * inv * g[c]);
}

// ---------------- host side --------------------------------------------------
static const int SMEM_G  = 2 * (128 * 72 + 64 * 136) * 2;   // 71680
static const int SMEM_FA = 4096 + 2 * 2 * 8704 * 2;         // 73728

template<bool OUTH, bool SILU, bool ROPE>
static void launch_gemm(const __half* A, const __half* B,
                        float* Cf, __half* Ch,
                        const float* bias, const float* resid, const __half* gateH,
                        int M, int N, int K, int lda, int ldb, int ldc, int ldr,
                        float scale) {
    dim3 grid(N / 128, M / 128), block(128);
    cudaFuncSetAttribute(hgemm_k<OUTH, SILU, ROPE>,
                         cudaFuncAttributeMaxDynamicSharedMemorySize, SMEM_G);
    hgemm_k<OUTH, SILU, ROPE><<<grid, block, SMEM_G>>>(
        A, B, Cf, Ch, bias, resid, gateH, M, N, K, lda, ldb, ldc, ldr, scale);
}

extern "C" void kernel_launch(void* const* d_in, const int* in_sizes, int n_in,
                              void* d_out, int out_size) {
    const float* enc    = (const float*)d_in[0];
    const float* mask   = (const float*)d_in[1];
    const float* gin    = (const float*)d_in[4];
    const float* gffn   = (const float*)d_in[5];
    const float* w_q    = (const float*)d_in[6];
    const float* b_q    = (const float*)d_in[7];
    const float* w_k    = (const float*)d_in[8];
    const float* b_k    = (const float*)d_in[9];
    const float* w_v    = (const float*)d_in[10];
    const float* b_v    = (const float*)d_in[11];
    const float* w_o    = (const float*)d_in[12];
    const float* b_o    = (const float*)d_in[13];
    const float* w_gate = (const float*)d_in[14];
    const float* b_gate = (const float*)d_in[15];
    const float* w_up   = (const float*)d_in[16];
    const float* b_up   = (const float*)d_in[17];
    const float* w_down = (const float*)d_in[18];
    const float* b_down = (const float*)d_in[19];
    float* out = (float*)d_out;

    float *ao, *bqkv;
    __half *wqkv, *woh, *wgh, *wuh, *wdh;
    __half *xnh, *qkv, *cxh, *hh, *gth, *guh;
    cudaGetSymbolAddress((void**)&ao,   g_ao);
    cudaGetSymbolAddress((void**)&bqkv, g_bqkv);
    cudaGetSymbolAddress((void**)&wqkv, g_wqkv);
    cudaGetSymbolAddress((void**)&woh,  g_woh);
    cudaGetSymbolAddress((void**)&wgh,  g_wgh);
    cudaGetSymbolAddress((void**)&wuh,  g_wuh);
    cudaGetSymbolAddress((void**)&wdh,  g_wdh);
    cudaGetSymbolAddress((void**)&xnh,  g_xnh);
    cudaGetSymbolAddress((void**)&qkv,  g_qkv);
    cudaGetSymbolAddress((void**)&cxh,  g_cxh);
    cudaGetSymbolAddress((void**)&hh,   g_hh);
    cudaGetSymbolAddress((void**)&gth,  g_gth);
    cudaGetSymbolAddress((void**)&guh,  g_guh);

    // 0) rope table + weights -> fp16 (q/k/v packed) + packed bias
    rope_tab_k<<<(S_ * (DH/2)) / 256, 256>>>();
    {
        long long tot = 5LL * SEG_BIG + 2LL * SEG_SM;
        f2h_all_k<<<(unsigned)(tot / 2048), 256>>>(
            w_q, w_k, w_v, w_o, w_gate, w_up, w_down,
            wqkv, woh, wgh, wuh, wdh);
        cudaMemcpyAsync(bqkv,            b_q, HD  * sizeof(float), cudaMemcpyDeviceToDevice);
        cudaMemcpyAsync(bqkv + HD,       b_k, KVD * sizeof(float), cudaMemcpyDeviceToDevice);
        cudaMemcpyAsync(bqkv + HD + KVD, b_v, KVD * sizeof(float), cudaMemcpyDeviceToDevice);
    }

    // 1) x = RMSNorm(enc) -> fp16
    rmsnorm_h<<<T_, 256>>>(enc, gin, xnh);

    // 2) fused QKV projection with RoPE in epilogue -> packed [T, 3072] fp16
    launch_gemm<true, false, true>(xnh, wqkv, nullptr, qkv, bqkv, nullptr, nullptr,
                                   T_, QKVN, HD, HD, QKVN, QKVN, 0, 1.0f);

    // 3-6) fused flash attention -> ctx fp16 [B,S,HD]
    {
        cudaFuncSetAttribute(flash_k, cudaFuncAttributeMaxDynamicSharedMemorySize, SMEM_FA);
        dim3 grid(S_ / 128, NH, B_);
        flash_k<<<grid, 256, SMEM_FA>>>(qkv, mask, cxh);
    }

    // 7) attn_out = enc + ctx @ w_o + b_o   (fp32)
    launch_gemm<false, false, false>(cxh, woh, ao, nullptr, b_o, enc, nullptr,
                                     T_, HD, HD, HD, HD, HD, HD, 1.0f);

    // 8) h = RMSNorm(attn_out) -> fp16
    rmsnorm_h<<<T_, 256>>>(ao, gffn, hh);

    // 9) gate proj -> fp16; up proj with fused SiLU(gate)*up -> fp16
    launch_gemm<true, false, false>(hh, wgh, nullptr, gth, b_gate, nullptr, nullptr,
                                    T_, HD, HD, HD, HD, HD, 0, 1.0f);
    launch_gemm<true, true, false>(hh, wuh, nullptr, guh, b_up, nullptr, gth,
                                   T_, HD, HD, HD, HD, HD, HD, 1.0f);

    // 10) out = attn_out + gu @ w_down + b_down
    launch_gemm<false, false, false>(guh, wdh, out, nullptr, b_down, ao, nullptr,
                                     T_, HD, HD, HD, HD, HD, HD, 1.0f);
}

// round 11
// speedup vs baseline: 1.0685x; 1.0685x over previous
#include <cuda_runtime.h>
#include <cuda_fp16.h>
#include <cstdint>
#include <math.h>

// ---------------- problem constants ----------------
#define B_   4
#define S_   1024
#define HD   2048
#define NH   16
#define NKV  4
#define DH   128
#define T_   (B_*S_)        // 4096
#define KVD  (NKV*DH)       // 512
#define QKVN (HD + 2*KVD)   // 3072 packed q|k|v columns
#define GUN  (2*HD)         // 4096 interleaved gate|up columns

// ---------------- scratch (device globals) ----------
__device__ float  g_ao  [(size_t)T_*HD];
__device__ float  g_bqkv[QKVN];
__device__ float  g_bgu [GUN];
__device__ float2 g_rope[S_ * (DH/2)];              // [s][d/2] -> (cos, sin)
__device__ __half g_wqkv[(size_t)HD*QKVN];
__device__ __half g_woh[(size_t)HD*HD];
__device__ __half g_wgu[(size_t)HD*GUN];
__device__ __half g_wdh[(size_t)HD*HD];
__device__ __half g_xnh[(size_t)T_*HD];
__device__ __half g_qkv[(size_t)T_*QKVN];
__device__ __half g_cxh[(size_t)T_*HD];
__device__ __half g_hh [(size_t)T_*HD];
__device__ __half g_guh[(size_t)T_*HD];

// ---------------- ptx helpers -----------------------
__device__ __forceinline__ void cpa16(unsigned int dst, const void* src) {
    asm volatile("cp.async.cg.shared.global [%0], [%1], 16;\n" :: "r"(dst), "l"(src));
}
__device__ __forceinline__ void cpa_commit() {
    asm volatile("cp.async.commit_group;\n");
}
template<int N>
__device__ __forceinline__ void cpa_wait() {
    asm volatile("cp.async.wait_group %0;\n" :: "n"(N));
}
__device__ __forceinline__ void ldsm4(unsigned &r0, unsigned &r1, unsigned &r2, unsigned &r3,
                                      unsigned int addr) {
    asm volatile("ldmatrix.sync.aligned.m8n8.x4.shared.b16 {%0,%1,%2,%3}, [%4];\n"
                 : "=r"(r0), "=r"(r1), "=r"(r2), "=r"(r3) : "r"(addr));
}
__device__ __forceinline__ void ldsm4t(unsigned &r0, unsigned &r1, unsigned &r2, unsigned &r3,
                                       unsigned int addr) {
    asm volatile("ldmatrix.sync.aligned.m8n8.x4.trans.shared.b16 {%0,%1,%2,%3}, [%4];\n"
                 : "=r"(r0), "=r"(r1), "=r"(r2), "=r"(r3) : "r"(addr));
}
__device__ __forceinline__ void mma16816(float c[4], const unsigned a[4], const unsigned b[2]) {
    asm volatile(
        "mma.sync.aligned.m16n8k16.row.col.f32.f16.f16.f32 "
        "{%0,%1,%2,%3},{%4,%5,%6,%7},{%8,%9},{%0,%1,%2,%3};\n"
        : "+f"(c[0]), "+f"(c[1]), "+f"(c[2]), "+f"(c[3])
        : "r"(a[0]), "r"(a[1]), "r"(a[2]), "r"(a[3]), "r"(b[0]), "r"(b[1]));
}
__device__ __forceinline__ unsigned packh2(float a, float b) {
    __half2 h = __floats2half2_rn(a, b);
    return *reinterpret_cast<unsigned*>(&h);
}

// ---------------- fp16 GEMM, 128x128 tile, BK=64, 2-stage (R9-proven) ------
// OUTH: fp16 out. SILU: interleaved gate|up columns; out col cn/2 gets
// silu(gate)*up, fp16 out (ldc = N/2 layout). ROPE: rotary on column pairs
// with cn < HD+KVD via g_rope (QKV projection only).
template<bool OUTH, bool SILU, bool ROPE>
__global__ __launch_bounds__(256, 2)
void hgemm_k(const __half* __restrict__ A, const __half* __restrict__ B,
             float* __restrict__ Cf, __half* __restrict__ Ch,
             const float* __restrict__ bias, const float* __restrict__ resid,
             int M, int N, int K, int lda, int ldb, int ldc, int ldr,
             float scale) {
    constexpr int ASTG = 128 * 72;    // halves: 128 rows x 64 (+8 pad)
    constexpr int BSTG = 64 * 136;    // halves: 64 k-rows x 128 (+8 pad)
    extern __shared__ __half sm[];
    __half* sA = sm;
    __half* sB = sm + 2 * ASTG;

    const int tid = threadIdx.x, lane = tid & 31, warp = tid >> 5;
    const int warpM = warp >> 2, warpN = warp & 3;
    const int m0 = blockIdx.y * 128, n0 = blockIdx.x * 128;

    const unsigned suA = (unsigned)__cvta_generic_to_shared(sA);
    const unsigned suB = (unsigned)__cvta_generic_to_shared(sB);

    const int arow = tid >> 3, acc8 = (tid & 7) * 8;
    const int brow = tid >> 4, bcc8 = (tid & 15) * 8;

    auto load_stage = [&](int kt, int buf) {
        const int k0 = kt << 6;
        #pragma unroll
        for (int i = 0; i < 4; i++) {
            int row = arow + i * 32;
            cpa16(suA + (unsigned)(buf * ASTG + row * 72 + acc8) * 2,
                  A + (long long)(m0 + row) * lda + k0 + acc8);
        }
        #pragma unroll
        for (int i = 0; i < 4; i++) {
            int kr = brow + i * 16;
            cpa16(suB + (unsigned)(buf * BSTG + kr * 136 + bcc8) * 2,
                  B + (long long)(k0 + kr) * ldb + n0 + bcc8);
        }
    };

    float acc[4][4][4];
    #pragma unroll
    for (int i = 0; i < 4; i++)
        #pragma unroll
        for (int j = 0; j < 4; j++)
            #pragma unroll
            for (int q = 0; q < 4; q++) acc[i][j][q] = 0.f;

    const int ktiles = K >> 6;
    load_stage(0, 0); cpa_commit();
    if (ktiles > 1) load_stage(1, 1);
    cpa_commit();

    for (int kt = 0; kt < ktiles; kt++) {
        const int buf = kt & 1;
        cpa_wait<1>();
        __syncthreads();

        #pragma unroll
        for (int kk = 0; kk < 4; kk++) {
            unsigned af[4][4], bf[4][2];
            const int ar = warpM * 64 + (lane & 15);
            const int ac = kk * 16 + (lane >> 4) * 8;
            #pragma unroll
            for (int i = 0; i < 4; i++)
                ldsm4(af[i][0], af[i][1], af[i][2], af[i][3],
                      suA + (unsigned)(buf * ASTG + (ar + i * 16) * 72 + ac) * 2);

            const int kr = kk * 16 + (lane & 15);
            const int ncl = (lane >> 4) * 8;
            #pragma unroll
            for (int jj = 0; jj < 2; jj++) {
                const int nb = warpN * 32 + jj * 16;
                ldsm4t(bf[jj*2][0], bf[jj*2][1], bf[jj*2+1][0], bf[jj*2+1][1],
                       suB + (unsigned)(buf * BSTG + kr * 136 + nb + ncl) * 2);
            }
            #pragma unroll
            for (int i = 0; i < 4; i++)
                #pragma unroll
                for (int j = 0; j < 4; j++)
                    mma16816(acc[i][j], af[i], bf[j]);
        }

        __syncthreads();                       // protect buf before overwrite
        if (kt + 2 < ktiles) load_stage(kt + 2, buf);
        cpa_commit();
    }

    #pragma unroll
    for (int i = 0; i < 4; i++) {
        const int r = m0 + warpM * 64 + i * 16 + (lane >> 2);
        #pragma unroll
        for (int j = 0; j < 4; j++) {
            const int cn = n0 + warpN * 32 + j * 8 + (lane & 3) * 2;
            float b0 = 0.f, b1 = 0.f;
            if (bias) { b0 = bias[cn]; b1 = bias[cn + 1]; }
            float v0 = acc[i][j][0] * scale + b0;
            float v1 = acc[i][j][1] * scale + b1;
            float v2 = acc[i][j][2] * scale + b0;
            float v3 = acc[i][j][3] * scale + b1;
            if (SILU) {
                // interleaved: v0=gate,v1=up (row r); v2=gate,v3=up (row r+8)
                float o0 = v0 / (1.0f + __expf(-v0)) * v1;
                float o1 = v2 / (1.0f + __expf(-v2)) * v3;
                Ch[(long long)r * ldc + (cn >> 1)]       = __float2half(o0);
                Ch[(long long)(r + 8) * ldc + (cn >> 1)] = __float2half(o1);
                continue;
            }
            if (ROPE) {
                if (cn < HD + KVD) {
                    const int pidx = (cn & (DH - 1)) >> 1;
                    const float2 t0 = g_rope[(r & (S_ - 1)) * (DH/2) + pidx];
                    const float2 t1 = g_rope[((r + 8) & (S_ - 1)) * (DH/2) + pidx];
                    float nv0 = t0.x * v0 - t0.y * v1;
                    float nv1 = t0.y * v0 + t0.x * v1;
                    float nv2 = t1.x * v2 - t1.y * v3;
                    float nv3 = t1.y * v2 + t1.x * v3;
                    v0 = nv0; v1 = nv1; v2 = nv2; v3 = nv3;
                }
            }
            if (resid) {
                const float* rr0 = &resid[(long long)r * ldr + cn];
                const float* rr1 = &resid[(long long)(r + 8) * ldr + cn];
                v0 += rr0[0]; v1 += rr0[1]; v2 += rr1[0]; v3 += rr1[1];
            }
            if (OUTH) {
                *reinterpret_cast<__half2*>(&Ch[(long long)r * ldc + cn]) =
                    __floats2half2_rn(v0, v1);
                *reinterpret_cast<__half2*>(&Ch[(long long)(r + 8) * ldc + cn]) =
                    __floats2half2_rn(v2, v3);
            } else {
                *reinterpret_cast<float2*>(&Cf[(long long)r * ldc + cn]) = make_float2(v0, v1);
                *reinterpret_cast<float2*>(&Cf[(long long)(r + 8) * ldc + cn]) = make_float2(v2, v3);
            }
        }
    }
}

// ---------------- FlashAttention-2 over packed qkv [T, 3072] ----------------
__global__ __launch_bounds__(256, 1)
void flash_k(const __half* __restrict__ qkv, const float* __restrict__ mask,
             __half* __restrict__ O) {
    extern __shared__ char smraw[];
    float* smask = (float*)smraw;
    const unsigned suKV = (unsigned)__cvta_generic_to_shared(smraw + 4096);

    const int tid = threadIdx.x, lane = tid & 31, warp = tid >> 5;
    const int s0 = blockIdx.x * 128;
    const int h = blockIdx.y, b = blockIdx.z;
    const int kvh = h / (NH / NKV);

    const __half* Qg = qkv + ((long long)(b * S_ + s0)) * QKVN + h * DH;
    const __half* Kg = qkv + ((long long)b * S_) * QKVN + HD + kvh * DH;
    const __half* Vg = qkv + ((long long)b * S_) * QKVN + HD + KVD + kvh * DH;

    for (int i = tid; i < S_ / 4; i += 256)
        *(float4*)&smask[i * 4] = *(const float4*)&mask[b * S_ + i * 4];

    #pragma unroll
    for (int i = 0; i < 8; i++) {
        int idx = tid + 256 * i;
        int row = idx >> 4, col = (idx & 15) * 8;
        cpa16(suKV + (unsigned)(row * 136 + col) * 2, Qg + (long long)row * QKVN + col);
    }
    cpa_commit();
    cpa_wait<0>();
    __syncthreads();

    unsigned af[8][4];
    {
        const int ar = warp * 16 + (lane & 15);
        const int ac = (lane >> 4) * 8;
        #pragma unroll
        for (int t = 0; t < 8; t++)
            ldsm4(af[t][0], af[t][1], af[t][2], af[t][3],
                  suKV + (unsigned)(ar * 136 + t * 16 + ac) * 2);
    }
    __syncthreads();

    auto load_kv = [&](int tile, int stage) {
        const int kv0 = tile * 64;
        const unsigned kb = suKV + (unsigned)(stage * 17408) * 2;
        const unsigned vbx = kb + 8704u * 2;
        #pragma unroll
        for (int i = 0; i < 4; i++) {
            int idx = tid + 256 * i;
            int row = idx >> 4, col = (idx & 15) * 8;
            cpa16(kb + (unsigned)(row * 136 + col) * 2,
                  Kg + (long long)(kv0 + row) * QKVN + col);
            cpa16(vbx + (unsigned)(row * 136 + col) * 2,
                  Vg + (long long)(kv0 + row) * QKVN + col);
        }
    };

    load_kv(0, 0); cpa_commit();
    load_kv(1, 1); cpa_commit();

    float oacc[16][4];
    #pragma unroll
    for (int d = 0; d < 16; d++)
        #pragma unroll
        for (int q = 0; q < 4; q++) oacc[d][q] = 0.f;

    float m0r = -INFINITY, m1r = -INFINITY, l0r = 0.f, l1r = 0.f;
    const int r0 = warp * 16 + (lane >> 2);
    const float mq0 = smask[s0 + r0];
    const float mq1 = smask[s0 + r0 + 8];
    const float scale = 0.08838834764831845f;

    for (int t = 0; t < 16; t++) {
        cpa_wait<1>();
        __syncthreads();
        const int stage = t & 1;
        const unsigned kb = suKV + (unsigned)(stage * 17408) * 2;
        const unsigned vbx = kb + 8704u * 2;

        float sacc[8][4];
        #pragma unroll
        for (int j = 0; j < 8; j++)
            #pragma unroll
            for (int q = 0; q < 4; q++) sacc[j][q] = 0.f;

        #pragma unroll
        for (int ks = 0; ks < 8; ks++) {
            unsigned bf[8][2];
            #pragma unroll
            for (int g = 0; g < 4; g++) {
                const int br = g * 16 + (lane >> 4) * 8 + (lane & 7);
                const int bc = ks * 16 + ((lane >> 3) & 1) * 8;
                ldsm4(bf[g*2][0], bf[g*2][1], bf[g*2+1][0], bf[g*2+1][1],
                      kb + (unsigned)(br * 136 + bc) * 2);
            }
            #pragma unroll
            for (int j = 0; j < 8; j++)
                mma16816(sacc[j], af[ks], bf[j]);
        }

        const int kvb = t * 64;
        float t0 = -INFINITY, t1 = -INFINITY;
        #pragma unroll
        for (int j = 0; j < 8; j++) {
            const int c = kvb + j * 8 + (lane & 3) * 2;
            const float mk0 = smask[c], mk1 = smask[c + 1];
            sacc[j][0] = (mq0 * mk0 == 0.f) ? -1e30f : sacc[j][0] * scale;
            sacc[j][1] = (mq0 * mk1 == 0.f) ? -1e30f : sacc[j][1] * scale;
            sacc[j][2] = (mq1 * mk0 == 0.f) ? -1e30f : sacc[j][2] * scale;
            sacc[j][3] = (mq1 * mk1 == 0.f) ? -1e30f : sacc[j][3] * scale;
            t0 = fmaxf(t0, fmaxf(sacc[j][0], sacc[j][1]));
            t1 = fmaxf(t1, fmaxf(sacc[j][2], sacc[j][3]));
        }
        t0 = fmaxf(t0, __shfl_xor_sync(0xffffffffu, t0, 1));
        t0 = fmaxf(t0, __shfl_xor_sync(0xffffffffu, t0, 2));
        t1 = fmaxf(t1, __shfl_xor_sync(0xffffffffu, t1, 1));
        t1 = fmaxf(t1, __shfl_xor_sync(0xffffffffu, t1, 2));

        const float mn0 = fmaxf(m0r, t0), mn1 = fmaxf(m1r, t1);
        const float a0 = __expf(m0r - mn0), a1 = __expf(m1r - mn1);
        m0r = mn0; m1r = mn1;

        float s0s = 0.f, s1s = 0.f;
        #pragma unroll
        for (int j = 0; j < 8; j++) {
            sacc[j][0] = __expf(sacc[j][0] - mn0);
            sacc[j][1] = __expf(sacc[j][1] - mn0);
            sacc[j][2] = __expf(sacc[j][2] - mn1);
            sacc[j][3] = __expf(sacc[j][3] - mn1);
            s0s += sacc[j][0] + sacc[j][1];
            s1s += sacc[j][2] + sacc[j][3];
        }
        s0s += __shfl_xor_sync(0xffffffffu, s0s, 1);
        s0s += __shfl_xor_sync(0xffffffffu, s0s, 2);
        s1s += __shfl_xor_sync(0xffffffffu, s1s, 1);
        s1s += __shfl_xor_sync(0xffffffffu, s1s, 2);
        l0r = l0r * a0 + s0s;
        l1r = l1r * a1 + s1s;

        #pragma unroll
        for (int d = 0; d < 16; d++) {
            oacc[d][0] *= a0; oacc[d][1] *= a0;
            oacc[d][2] *= a1; oacc[d][3] *= a1;
        }

        unsigned pa[4][4];
        #pragma unroll
        for (int kk = 0; kk < 4; kk++) {
            pa[kk][0] = packh2(sacc[2*kk][0],   sacc[2*kk][1]);
            pa[kk][1] = packh2(sacc[2*kk][2],   sacc[2*kk][3]);
            pa[kk][2] = packh2(sacc[2*kk+1][0], sacc[2*kk+1][1]);
            pa[kk][3] = packh2(sacc[2*kk+1][2], sacc[2*kk+1][3]);
        }

        #pragma unroll
        for (int kk = 0; kk < 4; kk++) {
            const int kr = kk * 16 + (lane & 15);
            const int ncl = (lane >> 4) * 8;
            unsigned vbf[16][2];
            #pragma unroll
            for (int dp = 0; dp < 8; dp++)
                ldsm4t(vbf[dp*2][0], vbf[dp*2][1], vbf[dp*2+1][0], vbf[dp*2+1][1],
                       vbx + (unsigned)(kr * 136 + dp * 16 + ncl) * 2);
            #pragma unroll
            for (int d = 0; d < 16; d++)
                mma16816(oacc[d], pa[kk], vbf[d]);
        }

        __syncthreads();
        if (t + 2 < 16) load_kv(t + 2, stage);
        cpa_commit();
    }

    const float i0 = 1.f / l0r, i1 = 1.f / l1r;
    __half* Og = O + ((long long)(b * S_ + s0 + r0)) * HD + h * DH;
    #pragma unroll
    for (int d = 0; d < 16; d++) {
        const int col = d * 8 + (lane & 3) * 2;
        *reinterpret_cast<__half2*>(&Og[col]) =
            __floats2half2_rn(oacc[d][0] * i0, oacc[d][1] * i0);
        *reinterpret_cast<__half2*>(&Og[(long long)8 * HD + col]) =
            __floats2half2_rn(oacc[d][2] * i1, oacc[d][3] * i1);
    }
}

// ---------------- elementwise kernels ---------------------------------------
__global__ void rope_tab_k() {
    int idx = blockIdx.x * blockDim.x + threadIdx.x;   // over S_ * DH/2
    if (idx >= S_ * (DH/2)) return;
    int s = idx >> 6, p = idx & 63;
    float inv = powf(10000.0f, -(float)(2 * p) / (float)DH);
    float ang = (float)s * inv;
    float sn, cs; sincosf(ang, &sn, &cs);
    g_rope[idx] = make_float2(cs, sn);
}

// weight convert: segments Q | K | V | O | GATE+UP(interleaved) | DOWN
#define SEG_BIG  (HD*HD)      // 4M
#define SEG_SM   (HD*KVD)     // 1M
__global__ void f2h_all_k(const float* __restrict__ wq, const float* __restrict__ wk,
                          const float* __restrict__ wv, const float* __restrict__ wo,
                          const float* __restrict__ wg, const float* __restrict__ wu,
                          const float* __restrict__ wd,
                          __half* __restrict__ wqkv, __half* __restrict__ oo,
                          __half* __restrict__ wgu, __half* __restrict__ od) {
    long long i = ((long long)blockIdx.x * blockDim.x + threadIdx.x) * 8;
    const long long big = SEG_BIG, sg = SEG_SM;
    if (i >= big + 2*sg + big && i < big + 2*sg + 2*big) {
        // GATE+UP interleave: off indexes gate space [row, j..j+7]
        long long off = i - big - 2*sg - big;
        long long row = off >> 11, j = off & 2047;
        float4 gA = *reinterpret_cast<const float4*>(&wg[off]);
        float4 gB = *reinterpret_cast<const float4*>(&wg[off + 4]);
        float4 uA = *reinterpret_cast<const float4*>(&wu[off]);
        float4 uB = *reinterpret_cast<const float4*>(&wu[off + 4]);
        __half* dst = wgu + row * GUN + 2 * j;    // 16 consecutive halves
        uint4 o0, o1;
        o0.x = packh2(gA.x, uA.x); o0.y = packh2(gA.y, uA.y);
        o0.z = packh2(gA.z, uA.z); o0.w = packh2(gA.w, uA.w);
        o1.x = packh2(gB.x, uB.x); o1.y = packh2(gB.y, uB.y);
        o1.z = packh2(gB.z, uB.z); o1.w = packh2(gB.w, uB.w);
        *reinterpret_cast<uint4*>(dst)     = o0;
        *reinterpret_cast<uint4*>(dst + 8) = o1;
        return;
    }
    const float* src; __half* dst; long long off, doff;
    if (i < big) {
        src = wq; off = i;
        doff = (off >> 11) * QKVN + (off & 2047);
        dst = wqkv;
    } else if (i < big + sg) {
        src = wk; off = i - big;
        doff = (off >> 9) * QKVN + HD + (off & 511);
        dst = wqkv;
    } else if (i < big + 2*sg) {
        src = wv; off = i - big - sg;
        doff = (off >> 9) * QKVN + HD + KVD + (off & 511);
        dst = wqkv;
    } else if (i < big + 2*sg + big) {
        src = wo; off = i - big - 2*sg; dst = oo; doff = off;
    } else {
        src = wd; off = i - big - 2*sg - 2*big; dst = od; doff = off;
    }
    float4 v0 = *reinterpret_cast<const float4*>(&src[off]);
    float4 v1 = *reinterpret_cast<const float4*>(&src[off + 4]);
    uint4 u;
    u.x = packh2(v0.x, v0.y); u.y = packh2(v0.z, v0.w);
    u.z = packh2(v1.x, v1.y); u.w = packh2(v1.z, v1.w);
    *reinterpret_cast<uint4*>(&dst[doff]) = u;
}

__global__ void bias_gu_k(const float* __restrict__ bg, const float* __restrict__ bu) {
    int j = blockIdx.x * blockDim.x + threadIdx.x;
    if (j >= HD) return;
    g_bgu[2*j]   = bg[j];
    g_bgu[2*j+1] = bu[j];
}

__global__ void rmsnorm_h(const float* __restrict__ x, const float* __restrict__ g,
                          __half* __restrict__ o) {
    __shared__ float sh[256];
    int row = blockIdx.x;
    const float* xr = x + (long long)row * HD;
    float s = 0.f;
    for (int c = threadIdx.x; c < HD; c += 256) { float v = xr[c]; s += v * v; }
    sh[threadIdx.x] = s; __syncthreads();
    for (int st = 128; st > 0; st >>= 1) {
        if (threadIdx.x < st) sh[threadIdx.x] += sh[threadIdx.x + st];
        __syncthreads();
    }
    float inv = 1.0f / sqrtf(sh[0] / (float)HD + 1e-8f);
    __half* orow = o + (long long)row * HD;
    for (int c = threadIdx.x; c < HD; c += 256)
        orow[c] = __float2half(xr[c] * inv * g[c]);
}

// ---------------- host side --------------------------------------------------
static const int SMEM_G  = 2 * (128 * 72 + 64 * 136) * 2;   // 71680
static const int SMEM_FA = 4096 + 2 * 2 * 8704 * 2;         // 73728

template<bool OUTH, bool SILU, bool ROPE>
static void launch_gemm(const __half* A, const __half* B,
                        float* Cf, __half* Ch,
                        const float* bias, const float* resid,
                        int M, int N, int K, int lda, int ldb, int ldc, int ldr,
                        float scale) {
    dim3 grid(N / 128, M / 128), block(256);
    cudaFuncSetAttribute(hgemm_k<OUTH, SILU, ROPE>,
                         cudaFuncAttributeMaxDynamicSharedMemorySize, SMEM_G);
    hgemm_k<OUTH, SILU, ROPE><<<grid, block, SMEM_G>>>(
        A, B, Cf, Ch, bias, resid, M, N, K, lda, ldb, ldc, ldr, scale);
}

extern "C" void kernel_launch(void* const* d_in, const int* in_sizes, int n_in,
                              void* d_out, int out_size) {
    const float* enc    = (const float*)d_in[0];
    const float* mask   = (const float*)d_in[1];
    const float* gin    = (const float*)d_in[4];
    const float* gffn   = (const float*)d_in[5];
    const float* w_q    = (const float*)d_in[6];
    const float* b_q    = (const float*)d_in[7];
    const float* w_k    = (const float*)d_in[8];
    const float* b_k    = (const float*)d_in[9];
    const float* w_v    = (const float*)d_in[10];
    const float* b_v    = (const float*)d_in[11];
    const float* w_o    = (const float*)d_in[12];
    const float* b_o    = (const float*)d_in[13];
    const float* w_gate = (const float*)d_in[14];
    const float* b_gate = (const float*)d_in[15];
    const float* w_up   = (const float*)d_in[16];
    const float* b_up   = (const float*)d_in[17];
    const float* w_down = (const float*)d_in[18];
    const float* b_down = (const float*)d_in[19];
    float* out = (float*)d_out;

    float *ao, *bqkv, *bgu;
    __half *wqkv, *woh, *wgu, *wdh;
    __half *xnh, *qkv, *cxh, *hh, *guh;
    cudaGetSymbolAddress((void**)&ao,   g_ao);
    cudaGetSymbolAddress((void**)&bqkv, g_bqkv);
    cudaGetSymbolAddress((void**)&bgu,  g_bgu);
    cudaGetSymbolAddress((void**)&wqkv, g_wqkv);
    cudaGetSymbolAddress((void**)&woh,  g_woh);
    cudaGetSymbolAddress((void**)&wgu,  g_wgu);
    cudaGetSymbolAddress((void**)&wdh,  g_wdh);
    cudaGetSymbolAddress((void**)&xnh,  g_xnh);
    cudaGetSymbolAddress((void**)&qkv,  g_qkv);
    cudaGetSymbolAddress((void**)&cxh,  g_cxh);
    cudaGetSymbolAddress((void**)&hh,   g_hh);
    cudaGetSymbolAddress((void**)&guh,  g_guh);

    // 0) rope table + weights -> fp16 (q/k/v packed, gate/up interleaved)
    rope_tab_k<<<(S_ * (DH/2)) / 256, 256>>>();
    {
        long long tot = 4LL * SEG_BIG + 2LL * SEG_SM;   // Q,O,GU,D big + K,V small
        f2h_all_k<<<(unsigned)(tot / 2048), 256>>>(
            w_q, w_k, w_v, w_o, w_gate, w_up, w_down,
            wqkv, woh, wgu, wdh);
        bias_gu_k<<<HD / 256, 256>>>(b_gate, b_up);
        cudaMemcpyAsync(bqkv,            b_q, HD  * sizeof(float), cudaMemcpyDeviceToDevice);
        cudaMemcpyAsync(bqkv + HD,       b_k, KVD * sizeof(float), cudaMemcpyDeviceToDevice);
        cudaMemcpyAsync(bqkv + HD + KVD, b_v, KVD * sizeof(float), cudaMemcpyDeviceToDevice);
    }

    // 1) x = RMSNorm(enc) -> fp16
    rmsnorm_h<<<T_, 256>>>(enc, gin, xnh);

    // 2) fused QKV projection with RoPE in epilogue -> packed [T, 3072] fp16
    launch_gemm<true, false, true>(xnh, wqkv, nullptr, qkv, bqkv, nullptr,
                                   T_, QKVN, HD, HD, QKVN, QKVN, 0, 1.0f);

    // 3-6) fused flash attention -> ctx fp16 [B,S,HD]
    {
        cudaFuncSetAttribute(flash_k, cudaFuncAttributeMaxDynamicSharedMemorySize, SMEM_FA);
        dim3 grid(S_ / 128, NH, B_);
        flash_k<<<grid, 256, SMEM_FA>>>(qkv, mask, cxh);
    }

    // 7) attn_out = enc + ctx @ w_o + b_o   (fp32)
    launch_gemm<false, false, false>(cxh, woh, ao, nullptr, b_o, enc,
                                     T_, HD, HD, HD, HD, HD, HD, 1.0f);

    // 8) h = RMSNorm(attn_out) -> fp16
    rmsnorm_h<<<T_, 256>>>(ao, gffn, hh);

    // 9) fused gate|up GEMM with SiLU epilogue -> guh fp16 [T, HD]
    launch_gemm<true, true, false>(hh, wgu, nullptr, guh, bgu, nullptr,
                                   T_, GUN, HD, HD, GUN, HD, 0, 1.0f);

    // 10) out = attn_out + gu @ w_down + b_down
    launch_gemm<false, false, false>(guh, wdh, out, nullptr, b_down, ao,
                                     T_, HD, HD, HD, HD, HD, HD, 1.0f);
}

// round 12
// speedup vs baseline: 1.1024x; 1.0318x over previous
#include <cuda_runtime.h>
#include <cuda_fp16.h>
#include <cstdint>
#include <math.h>

// ---------------- problem constants ----------------
#define B_   4
#define S_   1024
#define HD   2048
#define NH   16
#define NKV  4
#define DH   128
#define T_   (B_*S_)        // 4096
#define KVD  (NKV*DH)       // 512
#define QKVN (HD + 2*KVD)   // 3072 packed q|k|v columns
#define GUN  (2*HD)         // 4096 interleaved gate|up columns

// ---------------- scratch (device globals) ----------
__device__ float  g_ao  [(size_t)T_*HD];
__device__ float  g_bqkv[QKVN];
__device__ float  g_bgu [GUN];
__device__ float2 g_rope[S_ * (DH/2)];              // [s][d/2] -> (cos, sin)
__device__ __half g_wqkv[(size_t)HD*QKVN];
__device__ __half g_woh[(size_t)HD*HD];
__device__ __half g_wgu[(size_t)HD*GUN];
__device__ __half g_wdh[(size_t)HD*HD];
__device__ __half g_xnh[(size_t)T_*HD];
__device__ __half g_qkv[(size_t)T_*QKVN];
__device__ __half g_cxh[(size_t)T_*HD];
__device__ __half g_hh [(size_t)T_*HD];
__device__ __half g_guh[(size_t)T_*HD];

// ---------------- ptx helpers -----------------------
__device__ __forceinline__ void cpa16(unsigned int dst, const void* src) {
    asm volatile("cp.async.cg.shared.global [%0], [%1], 16;\n" :: "r"(dst), "l"(src));
}
__device__ __forceinline__ void cpa_commit() {
    asm volatile("cp.async.commit_group;\n");
}
template<int N>
__device__ __forceinline__ void cpa_wait() {
    asm volatile("cp.async.wait_group %0;\n" :: "n"(N));
}
__device__ __forceinline__ void ldsm4(unsigned &r0, unsigned &r1, unsigned &r2, unsigned &r3,
                                      unsigned int addr) {
    asm volatile("ldmatrix.sync.aligned.m8n8.x4.shared.b16 {%0,%1,%2,%3}, [%4];\n"
                 : "=r"(r0), "=r"(r1), "=r"(r2), "=r"(r3) : "r"(addr));
}
__device__ __forceinline__ void ldsm4t(unsigned &r0, unsigned &r1, unsigned &r2, unsigned &r3,
                                       unsigned int addr) {
    asm volatile("ldmatrix.sync.aligned.m8n8.x4.trans.shared.b16 {%0,%1,%2,%3}, [%4];\n"
                 : "=r"(r0), "=r"(r1), "=r"(r2), "=r"(r3) : "r"(addr));
}
__device__ __forceinline__ void mma16816(float c[4], const unsigned a[4], const unsigned b[2]) {
    asm volatile(
        "mma.sync.aligned.m16n8k16.row.col.f32.f16.f16.f32 "
        "{%0,%1,%2,%3},{%4,%5,%6,%7},{%8,%9},{%0,%1,%2,%3};\n"
        : "+f"(c[0]), "+f"(c[1]), "+f"(c[2]), "+f"(c[3])
        : "r"(a[0]), "r"(a[1]), "r"(a[2]), "r"(a[3]), "r"(b[0]), "r"(b[1]));
}
__device__ __forceinline__ unsigned packh2(float a, float b) {
    __half2 h = __floats2half2_rn(a, b);
    return *reinterpret_cast<unsigned*>(&h);
}

// ---------------- fp16 GEMM, 128x128 tile, BK=64, 2-stage (proven) ---------
// OUTH: fp16 out. SILU: interleaved gate|up columns; out col cn/2 gets
// silu(gate)*up, fp16 out (ldc = N/2 layout). ROPE: rotary on column pairs
// with cn < HD+KVD via g_rope (QKV projection only).
template<bool OUTH, bool SILU, bool ROPE>
__global__ __launch_bounds__(256, 2)
void hgemm_k(const __half* __restrict__ A, const __half* __restrict__ B,
             float* __restrict__ Cf, __half* __restrict__ Ch,
             const float* __restrict__ bias, const float* __restrict__ resid,
             int M, int N, int K, int lda, int ldb, int ldc, int ldr,
             float scale) {
    constexpr int ASTG = 128 * 72;    // halves: 128 rows x 64 (+8 pad)
    constexpr int BSTG = 64 * 136;    // halves: 64 k-rows x 128 (+8 pad)
    extern __shared__ __half sm[];
    __half* sA = sm;
    __half* sB = sm + 2 * ASTG;

    const int tid = threadIdx.x, lane = tid & 31, warp = tid >> 5;
    const int warpM = warp >> 2, warpN = warp & 3;
    const int m0 = blockIdx.y * 128, n0 = blockIdx.x * 128;

    const unsigned suA = (unsigned)__cvta_generic_to_shared(sA);
    const unsigned suB = (unsigned)__cvta_generic_to_shared(sB);

    const int arow = tid >> 3, acc8 = (tid & 7) * 8;
    const int brow = tid >> 4, bcc8 = (tid & 15) * 8;

    auto load_stage = [&](int kt, int buf) {
        const int k0 = kt << 6;
        #pragma unroll
        for (int i = 0; i < 4; i++) {
            int row = arow + i * 32;
            cpa16(suA + (unsigned)(buf * ASTG + row * 72 + acc8) * 2,
                  A + (long long)(m0 + row) * lda + k0 + acc8);
        }
        #pragma unroll
        for (int i = 0; i < 4; i++) {
            int kr = brow + i * 16;
            cpa16(suB + (unsigned)(buf * BSTG + kr * 136 + bcc8) * 2,
                  B + (long long)(k0 + kr) * ldb + n0 + bcc8);
        }
    };

    float acc[4][4][4];
    #pragma unroll
    for (int i = 0; i < 4; i++)
        #pragma unroll
        for (int j = 0; j < 4; j++)
            #pragma unroll
            for (int q = 0; q < 4; q++) acc[i][j][q] = 0.f;

    const int ktiles = K >> 6;
    load_stage(0, 0); cpa_commit();
    if (ktiles > 1) load_stage(1, 1);
    cpa_commit();

    for (int kt = 0; kt < ktiles; kt++) {
        const int buf = kt & 1;
        cpa_wait<1>();
        __syncthreads();

        #pragma unroll
        for (int kk = 0; kk < 4; kk++) {
            unsigned af[4][4], bf[4][2];
            const int ar = warpM * 64 + (lane & 15);
            const int ac = kk * 16 + (lane >> 4) * 8;
            #pragma unroll
            for (int i = 0; i < 4; i++)
                ldsm4(af[i][0], af[i][1], af[i][2], af[i][3],
                      suA + (unsigned)(buf * ASTG + (ar + i * 16) * 72 + ac) * 2);

            const int kr = kk * 16 + (lane & 15);
            const int ncl = (lane >> 4) * 8;
            #pragma unroll
            for (int jj = 0; jj < 2; jj++) {
                const int nb = warpN * 32 + jj * 16;
                ldsm4t(bf[jj*2][0], bf[jj*2][1], bf[jj*2+1][0], bf[jj*2+1][1],
                       suB + (unsigned)(buf * BSTG + kr * 136 + nb + ncl) * 2);
            }
            #pragma unroll
            for (int i = 0; i < 4; i++)
                #pragma unroll
                for (int j = 0; j < 4; j++)
                    mma16816(acc[i][j], af[i], bf[j]);
        }

        __syncthreads();                       // protect buf before overwrite
        if (kt + 2 < ktiles) load_stage(kt + 2, buf);
        cpa_commit();
    }

    #pragma unroll
    for (int i = 0; i < 4; i++) {
        const int r = m0 + warpM * 64 + i * 16 + (lane >> 2);
        #pragma unroll
        for (int j = 0; j < 4; j++) {
            const int cn = n0 + warpN * 32 + j * 8 + (lane & 3) * 2;
            float b0 = 0.f, b1 = 0.f;
            if (bias) { b0 = bias[cn]; b1 = bias[cn + 1]; }
            float v0 = acc[i][j][0] * scale + b0;
            float v1 = acc[i][j][1] * scale + b1;
            float v2 = acc[i][j][2] * scale + b0;
            float v3 = acc[i][j][3] * scale + b1;
            if (SILU) {
                float o0 = v0 / (1.0f + __expf(-v0)) * v1;
                float o1 = v2 / (1.0f + __expf(-v2)) * v3;
                Ch[(long long)r * ldc + (cn >> 1)]       = __float2half(o0);
                Ch[(long long)(r + 8) * ldc + (cn >> 1)] = __float2half(o1);
                continue;
            }
            if (ROPE) {
                if (cn < HD + KVD) {
                    const int pidx = (cn & (DH - 1)) >> 1;
                    const float2 t0 = g_rope[(r & (S_ - 1)) * (DH/2) + pidx];
                    const float2 t1 = g_rope[((r + 8) & (S_ - 1)) * (DH/2) + pidx];
                    float nv0 = t0.x * v0 - t0.y * v1;
                    float nv1 = t0.y * v0 + t0.x * v1;
                    float nv2 = t1.x * v2 - t1.y * v3;
                    float nv3 = t1.y * v2 + t1.x * v3;
                    v0 = nv0; v1 = nv1; v2 = nv2; v3 = nv3;
                }
            }
            if (resid) {
                const float* rr0 = &resid[(long long)r * ldr + cn];
                const float* rr1 = &resid[(long long)(r + 8) * ldr + cn];
                v0 += rr0[0]; v1 += rr0[1]; v2 += rr1[0]; v3 += rr1[1];
            }
            if (OUTH) {
                *reinterpret_cast<__half2*>(&Ch[(long long)r * ldc + cn]) =
                    __floats2half2_rn(v0, v1);
                *reinterpret_cast<__half2*>(&Ch[(long long)(r + 8) * ldc + cn]) =
                    __floats2half2_rn(v2, v3);
            } else {
                *reinterpret_cast<float2*>(&Cf[(long long)r * ldc + cn]) = make_float2(v0, v1);
                *reinterpret_cast<float2*>(&Cf[(long long)(r + 8) * ldc + cn]) = make_float2(v2, v3);
            }
        }
    }
}

// ---------------- FlashAttention-2 over packed qkv [T, 3072] ----------------
__global__ __launch_bounds__(256, 1)
void flash_k(const __half* __restrict__ qkv, const float* __restrict__ mask,
             __half* __restrict__ O) {
    extern __shared__ char smraw[];
    float* smask = (float*)smraw;
    const unsigned suKV = (unsigned)__cvta_generic_to_shared(smraw + 4096);

    const int tid = threadIdx.x, lane = tid & 31, warp = tid >> 5;
    const int s0 = blockIdx.x * 128;
    const int h = blockIdx.y, b = blockIdx.z;
    const int kvh = h / (NH / NKV);

    const __half* Qg = qkv + ((long long)(b * S_ + s0)) * QKVN + h * DH;
    const __half* Kg = qkv + ((long long)b * S_) * QKVN + HD + kvh * DH;
    const __half* Vg = qkv + ((long long)b * S_) * QKVN + HD + KVD + kvh * DH;

    for (int i = tid; i < S_ / 4; i += 256)
        *(float4*)&smask[i * 4] = *(const float4*)&mask[b * S_ + i * 4];

    #pragma unroll
    for (int i = 0; i < 8; i++) {
        int idx = tid + 256 * i;
        int row = idx >> 4, col = (idx & 15) * 8;
        cpa16(suKV + (unsigned)(row * 136 + col) * 2, Qg + (long long)row * QKVN + col);
    }
    cpa_commit();
    cpa_wait<0>();
    __syncthreads();

    unsigned af[8][4];
    {
        const int ar = warp * 16 + (lane & 15);
        const int ac = (lane >> 4) * 8;
        #pragma unroll
        for (int t = 0; t < 8; t++)
            ldsm4(af[t][0], af[t][1], af[t][2], af[t][3],
                  suKV + (unsigned)(ar * 136 + t * 16 + ac) * 2);
    }
    __syncthreads();

    auto load_kv = [&](int tile, int stage) {
        const int kv0 = tile * 64;
        const unsigned kb = suKV + (unsigned)(stage * 17408) * 2;
        const unsigned vbx = kb + 8704u * 2;
        #pragma unroll
        for (int i = 0; i < 4; i++) {
            int idx = tid + 256 * i;
            int row = idx >> 4, col = (idx & 15) * 8;
            cpa16(kb + (unsigned)(row * 136 + col) * 2,
                  Kg + (long long)(kv0 + row) * QKVN + col);
            cpa16(vbx + (unsigned)(row * 136 + col) * 2,
                  Vg + (long long)(kv0 + row) * QKVN + col);
        }
    };

    load_kv(0, 0); cpa_commit();
    load_kv(1, 1); cpa_commit();

    float oacc[16][4];
    #pragma unroll
    for (int d = 0; d < 16; d++)
        #pragma unroll
        for (int q = 0; q < 4; q++) oacc[d][q] = 0.f;

    float m0r = -INFINITY, m1r = -INFINITY, l0r = 0.f, l1r = 0.f;
    const int r0 = warp * 16 + (lane >> 2);
    const float mq0 = smask[s0 + r0];
    const float mq1 = smask[s0 + r0 + 8];
    const float scale = 0.08838834764831845f;

    for (int t = 0; t < 16; t++) {
        cpa_wait<1>();
        __syncthreads();
        const int stage = t & 1;
        const unsigned kb = suKV + (unsigned)(stage * 17408) * 2;
        const unsigned vbx = kb + 8704u * 2;

        float sacc[8][4];
        #pragma unroll
        for (int j = 0; j < 8; j++)
            #pragma unroll
            for (int q = 0; q < 4; q++) sacc[j][q] = 0.f;

        #pragma unroll
        for (int ks = 0; ks < 8; ks++) {
            unsigned bf[8][2];
            #pragma unroll
            for (int g = 0; g < 4; g++) {
                const int br = g * 16 + (lane >> 4) * 8 + (lane & 7);
                const int bc = ks * 16 + ((lane >> 3) & 1) * 8;
                ldsm4(bf[g*2][0], bf[g*2][1], bf[g*2+1][0], bf[g*2+1][1],
                      kb + (unsigned)(br * 136 + bc) * 2);
            }
            #pragma unroll
            for (int j = 0; j < 8; j++)
                mma16816(sacc[j], af[ks], bf[j]);
        }

        const int kvb = t * 64;
        float t0 = -INFINITY, t1 = -INFINITY;
        #pragma unroll
        for (int j = 0; j < 8; j++) {
            const int c = kvb + j * 8 + (lane & 3) * 2;
            const float mk0 = smask[c], mk1 = smask[c + 1];
            sacc[j][0] = (mq0 * mk0 == 0.f) ? -1e30f : sacc[j][0] * scale;
            sacc[j][1] = (mq0 * mk1 == 0.f) ? -1e30f : sacc[j][1] * scale;
            sacc[j][2] = (mq1 * mk0 == 0.f) ? -1e30f : sacc[j][2] * scale;
            sacc[j][3] = (mq1 * mk1 == 0.f) ? -1e30f : sacc[j][3] * scale;
            t0 = fmaxf(t0, fmaxf(sacc[j][0], sacc[j][1]));
            t1 = fmaxf(t1, fmaxf(sacc[j][2], sacc[j][3]));
        }
        t0 = fmaxf(t0, __shfl_xor_sync(0xffffffffu, t0, 1));
        t0 = fmaxf(t0, __shfl_xor_sync(0xffffffffu, t0, 2));
        t1 = fmaxf(t1, __shfl_xor_sync(0xffffffffu, t1, 1));
        t1 = fmaxf(t1, __shfl_xor_sync(0xffffffffu, t1, 2));

        const float mn0 = fmaxf(m0r, t0), mn1 = fmaxf(m1r, t1);
        const float a0 = __expf(m0r - mn0), a1 = __expf(m1r - mn1);
        m0r = mn0; m1r = mn1;

        float s0s = 0.f, s1s = 0.f;
        #pragma unroll
        for (int j = 0; j < 8; j++) {
            sacc[j][0] = __expf(sacc[j][0] - mn0);
            sacc[j][1] = __expf(sacc[j][1] - mn0);
            sacc[j][2] = __expf(sacc[j][2] - mn1);
            sacc[j][3] = __expf(sacc[j][3] - mn1);
            s0s += sacc[j][0] + sacc[j][1];
            s1s += sacc[j][2] + sacc[j][3];
        }
        s0s += __shfl_xor_sync(0xffffffffu, s0s, 1);
        s0s += __shfl_xor_sync(0xffffffffu, s0s, 2);
        s1s += __shfl_xor_sync(0xffffffffu, s1s, 1);
        s1s += __shfl_xor_sync(0xffffffffu, s1s, 2);
        l0r = l0r * a0 + s0s;
        l1r = l1r * a1 + s1s;

        #pragma unroll
        for (int d = 0; d < 16; d++) {
            oacc[d][0] *= a0; oacc[d][1] *= a0;
            oacc[d][2] *= a1; oacc[d][3] *= a1;
        }

        unsigned pa[4][4];
        #pragma unroll
        for (int kk = 0; kk < 4; kk++) {
            pa[kk][0] = packh2(sacc[2*kk][0],   sacc[2*kk][1]);
            pa[kk][1] = packh2(sacc[2*kk][2],   sacc[2*kk][3]);
            pa[kk][2] = packh2(sacc[2*kk+1][0], sacc[2*kk+1][1]);
            pa[kk][3] = packh2(sacc[2*kk+1][2], sacc[2*kk+1][3]);
        }

        #pragma unroll
        for (int kk = 0; kk < 4; kk++) {
            const int kr = kk * 16 + (lane & 15);
            const int ncl = (lane >> 4) * 8;
            unsigned vbf[16][2];
            #pragma unroll
            for (int dp = 0; dp < 8; dp++)
                ldsm4t(vbf[dp*2][0], vbf[dp*2][1], vbf[dp*2+1][0], vbf[dp*2+1][1],
                       vbx + (unsigned)(kr * 136 + dp * 16 + ncl) * 2);
            #pragma unroll
            for (int d = 0; d < 16; d++)
                mma16816(oacc[d], pa[kk], vbf[d]);
        }

        __syncthreads();
        if (t + 2 < 16) load_kv(t + 2, stage);
        cpa_commit();
    }

    const float i0 = 1.f / l0r, i1 = 1.f / l1r;
    __half* Og = O + ((long long)(b * S_ + s0 + r0)) * HD + h * DH;
    #pragma unroll
    for (int d = 0; d < 16; d++) {
        const int col = d * 8 + (lane & 3) * 2;
        *reinterpret_cast<__half2*>(&Og[col]) =
            __floats2half2_rn(oacc[d][0] * i0, oacc[d][1] * i0);
        *reinterpret_cast<__half2*>(&Og[(long long)8 * HD + col]) =
            __floats2half2_rn(oacc[d][2] * i1, oacc[d][3] * i1);
    }
}

// ---------------- elementwise kernels ---------------------------------------
__global__ void rope_tab_k() {
    int idx = blockIdx.x * blockDim.x + threadIdx.x;   // over S_ * DH/2
    if (idx >= S_ * (DH/2)) return;
    int s = idx >> 6, p = idx & 63;
    float inv = powf(10000.0f, -(float)(2 * p) / (float)DH);
    float ang = (float)s * inv;
    float sn, cs; sincosf(ang, &sn, &cs);
    g_rope[idx] = make_float2(cs, sn);
}

// weight convert: segments Q | K | V | O | GATE+UP(interleaved) | DOWN
#define SEG_BIG  (HD*HD)      // 4M
#define SEG_SM   (HD*KVD)     // 1M
__global__ void f2h_all_k(const float* __restrict__ wq, const float* __restrict__ wk,
                          const float* __restrict__ wv, const float* __restrict__ wo,
                          const float* __restrict__ wg, const float* __restrict__ wu,
                          const float* __restrict__ wd,
                          __half* __restrict__ wqkv, __half* __restrict__ oo,
                          __half* __restrict__ wgu, __half* __restrict__ od) {
    long long i = ((long long)blockIdx.x * blockDim.x + threadIdx.x) * 8;
    const long long big = SEG_BIG, sg = SEG_SM;
    if (i >= big + 2*sg + big && i < big + 2*sg + 2*big) {
        long long off = i - big - 2*sg - big;
        long long row = off >> 11, j = off & 2047;
        float4 gA = *reinterpret_cast<const float4*>(&wg[off]);
        float4 gB = *reinterpret_cast<const float4*>(&wg[off + 4]);
        float4 uA = *reinterpret_cast<const float4*>(&wu[off]);
        float4 uB = *reinterpret_cast<const float4*>(&wu[off + 4]);
        __half* dst = wgu + row * GUN + 2 * j;
        uint4 o0, o1;
        o0.x = packh2(gA.x, uA.x); o0.y = packh2(gA.y, uA.y);
        o0.z = packh2(gA.z, uA.z); o0.w = packh2(gA.w, uA.w);
        o1.x = packh2(gB.x, uB.x); o1.y = packh2(gB.y, uB.y);
        o1.z = packh2(gB.z, uB.z); o1.w = packh2(gB.w, uB.w);
        *reinterpret_cast<uint4*>(dst)     = o0;
        *reinterpret_cast<uint4*>(dst + 8) = o1;
        return;
    }
    const float* src; __half* dst; long long off, doff;
    if (i < big) {
        src = wq; off = i;
        doff = (off >> 11) * QKVN + (off & 2047);
        dst = wqkv;
    } else if (i < big + sg) {
        src = wk; off = i - big;
        doff = (off >> 9) * QKVN + HD + (off & 511);
        dst = wqkv;
    } else if (i < big + 2*sg) {
        src = wv; off = i - big - sg;
        doff = (off >> 9) * QKVN + HD + KVD + (off & 511);
        dst = wqkv;
    } else if (i < big + 2*sg + big) {
        src = wo; off = i - big - 2*sg; dst = oo; doff = off;
    } else {
        src = wd; off = i - big - 2*sg - 2*big; dst = od; doff = off;
    }
    float4 v0 = *reinterpret_cast<const float4*>(&src[off]);
    float4 v1 = *reinterpret_cast<const float4*>(&src[off + 4]);
    uint4 u;
    u.x = packh2(v0.x, v0.y); u.y = packh2(v0.z, v0.w);
    u.z = packh2(v1.x, v1.y); u.w = packh2(v1.z, v1.w);
    *reinterpret_cast<uint4*>(&dst[doff]) = u;
}

__global__ void bias_gu_k(const float* __restrict__ bg, const float* __restrict__ bu) {
    int j = blockIdx.x * blockDim.x + threadIdx.x;
    if (j >= HD) return;
    g_bgu[2*j]   = bg[j];
    g_bgu[2*j+1] = bu[j];
}

// fast RMSNorm: 256 threads/row; single pass (values in regs), float4 loads,
// warp-shuffle reduction, uint4 (8 halves) store.
__global__ void rmsnorm_h(const float* __restrict__ x, const float* __restrict__ g,
                          __half* __restrict__ o) {
    __shared__ float swarp[8];
    const int row = blockIdx.x, tid = threadIdx.x;
    const int lane = tid & 31, warp = tid >> 5;
    const float* xr = x + (long long)row * HD + tid * 8;

    float4 a = *reinterpret_cast<const float4*>(xr);
    float4 b = *reinterpret_cast<const float4*>(xr + 4);
    float s = a.x*a.x + a.y*a.y + a.z*a.z + a.w*a.w
            + b.x*b.x + b.y*b.y + b.z*b.z + b.w*b.w;
    #pragma unroll
    for (int st = 16; st > 0; st >>= 1)
        s += __shfl_xor_sync(0xffffffffu, s, st);
    if (lane == 0) swarp[warp] = s;
    __syncthreads();
    if (warp == 0) {
        float t = (lane < 8) ? swarp[lane] : 0.f;
        #pragma unroll
        for (int st = 4; st > 0; st >>= 1)
            t += __shfl_xor_sync(0xffffffffu, t, st);
        if (lane == 0) swarp[0] = t;
    }
    __syncthreads();
    const float inv = rsqrtf(swarp[0] / (float)HD + 1e-8f);

    const float* gr = g + tid * 8;
    float4 ga = *reinterpret_cast<const float4*>(gr);
    float4 gb = *reinterpret_cast<const float4*>(gr + 4);
    uint4 u;
    u.x = packh2(a.x * inv * ga.x, a.y * inv * ga.y);
    u.y = packh2(a.z * inv * ga.z, a.w * inv * ga.w);
    u.z = packh2(b.x * inv * gb.x, b.y * inv * gb.y);
    u.w = packh2(b.z * inv * gb.z, b.w * inv * gb.w);
    *reinterpret_cast<uint4*>(o + (long long)row * HD + tid * 8) = u;
}

// ---------------- host side --------------------------------------------------
static const int SMEM_G  = 2 * (128 * 72 + 64 * 136) * 2;   // 71680
static const int SMEM_FA = 4096 + 2 * 2 * 8704 * 2;         // 73728

template<bool OUTH, bool SILU, bool ROPE>
static void launch_gemm(const __half* A, const __half* B,
                        float* Cf, __half* Ch,
                        const float* bias, const float* resid,
                        int M, int N, int K, int lda, int ldb, int ldc, int ldr,
                        float scale) {
    dim3 grid(N / 128, M / 128), block(256);
    cudaFuncSetAttribute(hgemm_k<OUTH, SILU, ROPE>,
                         cudaFuncAttributeMaxDynamicSharedMemorySize, SMEM_G);
    hgemm_k<OUTH, SILU, ROPE><<<grid, block, SMEM_G>>>(
        A, B, Cf, Ch, bias, resid, M, N, K, lda, ldb, ldc, ldr, scale);
}

extern "C" void kernel_launch(void* const* d_in, const int* in_sizes, int n_in,
                              void* d_out, int out_size) {
    const float* enc    = (const float*)d_in[0];
    const float* mask   = (const float*)d_in[1];
    const float* gin    = (const float*)d_in[4];
    const float* gffn   = (const float*)d_in[5];
    const float* w_q    = (const float*)d_in[6];
    const float* b_q    = (const float*)d_in[7];
    const float* w_k    = (const float*)d_in[8];
    const float* b_k    = (const float*)d_in[9];
    const float* w_v    = (const float*)d_in[10];
    const float* b_v    = (const float*)d_in[11];
    const float* w_o    = (const float*)d_in[12];
    const float* b_o    = (const float*)d_in[13];
    const float* w_gate = (const float*)d_in[14];
    const float* b_gate = (const float*)d_in[15];
    const float* w_up   = (const float*)d_in[16];
    const float* b_up   = (const float*)d_in[17];
    const float* w_down = (const float*)d_in[18];
    const float* b_down = (const float*)d_in[19];
    float* out = (float*)d_out;

    float *ao, *bqkv, *bgu;
    __half *wqkv, *woh, *wgu, *wdh;
    __half *xnh, *qkv, *cxh, *hh, *guh;
    cudaGetSymbolAddress((void**)&ao,   g_ao);
    cudaGetSymbolAddress((void**)&bqkv, g_bqkv);
    cudaGetSymbolAddress((void**)&bgu,  g_bgu);
    cudaGetSymbolAddress((void**)&wqkv, g_wqkv);
    cudaGetSymbolAddress((void**)&woh,  g_woh);
    cudaGetSymbolAddress((void**)&wgu,  g_wgu);
    cudaGetSymbolAddress((void**)&wdh,  g_wdh);
    cudaGetSymbolAddress((void**)&xnh,  g_xnh);
    cudaGetSymbolAddress((void**)&qkv,  g_qkv);
    cudaGetSymbolAddress((void**)&cxh,  g_cxh);
    cudaGetSymbolAddress((void**)&hh,   g_hh);
    cudaGetSymbolAddress((void**)&guh,  g_guh);

    // 0) rope table + weights -> fp16 (q/k/v packed, gate/up interleaved)
    rope_tab_k<<<(S_ * (DH/2)) / 256, 256>>>();
    {
        long long tot = 4LL * SEG_BIG + 2LL * SEG_SM;
        f2h_all_k<<<(unsigned)(tot / 2048), 256>>>(
            w_q, w_k, w_v, w_o, w_gate, w_up, w_down,
            wqkv, woh, wgu, wdh);
        bias_gu_k<<<HD / 256, 256>>>(b_gate, b_up);
        cudaMemcpyAsync(bqkv,            b_q, HD  * sizeof(float), cudaMemcpyDeviceToDevice);
        cudaMemcpyAsync(bqkv + HD,       b_k, KVD * sizeof(float), cudaMemcpyDeviceToDevice);
        cudaMemcpyAsync(bqkv + HD + KVD, b_v, KVD * sizeof(float), cudaMemcpyDeviceToDevice);
    }

    // 1) x = RMSNorm(enc) -> fp16
    rmsnorm_h<<<T_, 256>>>(enc, gin, xnh);

    // 2) fused QKV projection with RoPE in epilogue -> packed [T, 3072] fp16
    launch_gemm<true, false, true>(xnh, wqkv, nullptr, qkv, bqkv, nullptr,
                                   T_, QKVN, HD, HD, QKVN, QKVN, 0, 1.0f);

    // 3-6) fused flash attention -> ctx fp16 [B,S,HD]
    {
        cudaFuncSetAttribute(flash_k, cudaFuncAttributeMaxDynamicSharedMemorySize, SMEM_FA);
        dim3 grid(S_ / 128, NH, B_);
        flash_k<<<grid, 256, SMEM_FA>>>(qkv, mask, cxh);
    }

    // 7) attn_out = enc + ctx @ w_o + b_o   (fp32)
    launch_gemm<false, false, false>(cxh, woh, ao, nullptr, b_o, enc,
                                     T_, HD, HD, HD, HD, HD, HD, 1.0f);

    // 8) h = RMSNorm(attn_out) -> fp16
    rmsnorm_h<<<T_, 256>>>(ao, gffn, hh);

    // 9) fused gate|up GEMM with SiLU epilogue -> guh fp16 [T, HD]
    launch_gemm<true, true, false>(hh, wgu, nullptr, guh, bgu, nullptr,
                                   T_, GUN, HD, HD, GUN, HD, 0, 1.0f);

    // 10) out = attn_out + gu @ w_down + b_down
    launch_gemm<false, false, false>(guh, wdh, out, nullptr, b_down, ao,
                                     T_, HD, HD, HD, HD, HD, HD, 1.0f);
}

// round 13
// speedup vs baseline: 1.1047x; 1.0020x over previous
#include <cuda_runtime.h>
#include <cuda_fp16.h>
#include <cstdint>
#include <math.h>

// ---------------- problem constants ----------------
#define B_   4
#define S_   1024
#define HD   2048
#define NH   16
#define NKV  4
#define DH   128
#define T_   (B_*S_)        // 4096
#define KVD  (NKV*DH)       // 512
#define QKVN (HD + 2*KVD)   // 3072 packed q|k|v columns
#define GUN  (2*HD)         // 4096 interleaved gate|up columns

// ---------------- scratch (device globals) ----------
__device__ float  g_ao  [(size_t)T_*HD];
__device__ float  g_bqkv[QKVN];
__device__ float  g_bgu [GUN];
__device__ float2 g_rope[S_ * (DH/2)];              // [s][d/2] -> (cos, sin)
__device__ __half g_wqkv[(size_t)HD*QKVN];
__device__ __half g_woh[(size_t)HD*HD];
__device__ __half g_wgu[(size_t)HD*GUN];
__device__ __half g_wdh[(size_t)HD*HD];
__device__ __half g_xnh[(size_t)T_*HD];
__device__ __half g_qkv[(size_t)T_*QKVN];
__device__ __half g_cxh[(size_t)T_*HD];
__device__ __half g_hh [(size_t)T_*HD];
__device__ __half g_guh[(size_t)T_*HD];

// ---------------- ptx helpers -----------------------
__device__ __forceinline__ void cpa16(unsigned int dst, const void* src) {
    asm volatile("cp.async.cg.shared.global [%0], [%1], 16;\n" :: "r"(dst), "l"(src));
}
__device__ __forceinline__ void cpa_commit() {
    asm volatile("cp.async.commit_group;\n");
}
template<int N>
__device__ __forceinline__ void cpa_wait() {
    asm volatile("cp.async.wait_group %0;\n" :: "n"(N));
}
__device__ __forceinline__ void ldsm4(unsigned &r0, unsigned &r1, unsigned &r2, unsigned &r3,
                                      unsigned int addr) {
    asm volatile("ldmatrix.sync.aligned.m8n8.x4.shared.b16 {%0,%1,%2,%3}, [%4];\n"
                 : "=r"(r0), "=r"(r1), "=r"(r2), "=r"(r3) : "r"(addr));
}
__device__ __forceinline__ void ldsm4t(unsigned &r0, unsigned &r1, unsigned &r2, unsigned &r3,
                                       unsigned int addr) {
    asm volatile("ldmatrix.sync.aligned.m8n8.x4.trans.shared.b16 {%0,%1,%2,%3}, [%4];\n"
                 : "=r"(r0), "=r"(r1), "=r"(r2), "=r"(r3) : "r"(addr));
}
__device__ __forceinline__ void mma16816(float c[4], const unsigned a[4], const unsigned b[2]) {
    asm volatile(
        "mma.sync.aligned.m16n8k16.row.col.f32.f16.f16.f32 "
        "{%0,%1,%2,%3},{%4,%5,%6,%7},{%8,%9},{%0,%1,%2,%3};\n"
        : "+f"(c[0]), "+f"(c[1]), "+f"(c[2]), "+f"(c[3])
        : "r"(a[0]), "r"(a[1]), "r"(a[2]), "r"(a[3]), "r"(b[0]), "r"(b[1]));
}
__device__ __forceinline__ unsigned packh2(float a, float b) {
    __half2 h = __floats2half2_rn(a, b);
    return *reinterpret_cast<unsigned*>(&h);
}

// ---------------- fp16 GEMM, 128x128 tile, BK=64, 3-stage, 1 sync/iter -----
// OUTH: fp16 out. SILU: interleaved gate|up columns; out col cn/2 gets
// silu(gate)*up, fp16 out (ldc = N/2 layout). ROPE: rotary on column pairs
// with cn < HD+KVD via g_rope (QKV projection only).
template<bool OUTH, bool SILU, bool ROPE>
__global__ __launch_bounds__(256, 2)
void hgemm_k(const __half* __restrict__ A, const __half* __restrict__ B,
             float* __restrict__ Cf, __half* __restrict__ Ch,
             const float* __restrict__ bias, const float* __restrict__ resid,
             int M, int N, int K, int lda, int ldb, int ldc, int ldr,
             float scale) {
    constexpr int ASTG = 128 * 72;    // halves: 128 rows x 64 (+8 pad)
    constexpr int BSTG = 64 * 136;    // halves: 64 k-rows x 128 (+8 pad)
    constexpr int STG  = ASTG + BSTG; // halves per stage
    extern __shared__ __half sm[];

    const int tid = threadIdx.x, lane = tid & 31, warp = tid >> 5;
    const int warpM = warp >> 2, warpN = warp & 3;
    const int m0 = blockIdx.y * 128, n0 = blockIdx.x * 128;

    const unsigned su = (unsigned)__cvta_generic_to_shared(sm);

    const int arow = tid >> 3, acc8 = (tid & 7) * 8;
    const int brow = tid >> 4, bcc8 = (tid & 15) * 8;

    auto load_stage = [&](int kt, int buf) {
        const int k0 = kt << 6;
        const unsigned sa = su + (unsigned)(buf * STG) * 2;
        const unsigned sb = sa + (unsigned)ASTG * 2;
        #pragma unroll
        for (int i = 0; i < 4; i++) {
            int row = arow + i * 32;
            cpa16(sa + (unsigned)(row * 72 + acc8) * 2,
                  A + (long long)(m0 + row) * lda + k0 + acc8);
        }
        #pragma unroll
        for (int i = 0; i < 4; i++) {
            int kr = brow + i * 16;
            cpa16(sb + (unsigned)(kr * 136 + bcc8) * 2,
                  B + (long long)(k0 + kr) * ldb + n0 + bcc8);
        }
    };

    float acc[4][4][4];
    #pragma unroll
    for (int i = 0; i < 4; i++)
        #pragma unroll
        for (int j = 0; j < 4; j++)
            #pragma unroll
            for (int q = 0; q < 4; q++) acc[i][j][q] = 0.f;

    const int ktiles = K >> 6;
    load_stage(0, 0); cpa_commit();
    if (ktiles > 1) load_stage(1, 1);
    cpa_commit();

    int buf = 0;
    for (int kt = 0; kt < ktiles; kt++) {
        cpa_wait<1>();
        __syncthreads();

        // issue next-next stage load BEFORE compute (buf (kt+2)%3 was last
        // read in iteration kt-1; the sync above retires those reads)
        {
            int pf = kt + 2;
            if (pf < ktiles) {
                int pbuf = buf + 2; if (pbuf >= 3) pbuf -= 3;
                load_stage(pf, pbuf);
            }
            cpa_commit();
        }

        const unsigned sa = su + (unsigned)(buf * STG) * 2;
        const unsigned sb = sa + (unsigned)ASTG * 2;

        #pragma unroll
        for (int kk = 0; kk < 4; kk++) {
            unsigned af[4][4], bf[4][2];
            const int ar = warpM * 64 + (lane & 15);
            const int ac = kk * 16 + (lane >> 4) * 8;
            #pragma unroll
            for (int i = 0; i < 4; i++)
                ldsm4(af[i][0], af[i][1], af[i][2], af[i][3],
                      sa + (unsigned)((ar + i * 16) * 72 + ac) * 2);

            const int kr = kk * 16 + (lane & 15);
            const int ncl = (lane >> 4) * 8;
            #pragma unroll
            for (int jj = 0; jj < 2; jj++) {
                const int nb = warpN * 32 + jj * 16;
                ldsm4t(bf[jj*2][0], bf[jj*2][1], bf[jj*2+1][0], bf[jj*2+1][1],
                       sb + (unsigned)(kr * 136 + nb + ncl) * 2);
            }
            #pragma unroll
            for (int i = 0; i < 4; i++)
                #pragma unroll
                for (int j = 0; j < 4; j++)
                    mma16816(acc[i][j], af[i], bf[j]);
        }
        buf++; if (buf >= 3) buf -= 3;
    }

    #pragma unroll
    for (int i = 0; i < 4; i++) {
        const int r = m0 + warpM * 64 + i * 16 + (lane >> 2);
        #pragma unroll
        for (int j = 0; j < 4; j++) {
            const int cn = n0 + warpN * 32 + j * 8 + (lane & 3) * 2;
            float b0 = 0.f, b1 = 0.f;
            if (bias) { b0 = bias[cn]; b1 = bias[cn + 1]; }
            float v0 = acc[i][j][0] * scale + b0;
            float v1 = acc[i][j][1] * scale + b1;
            float v2 = acc[i][j][2] * scale + b0;
            float v3 = acc[i][j][3] * scale + b1;
            if (SILU) {
                float o0 = v0 / (1.0f + __expf(-v0)) * v1;
                float o1 = v2 / (1.0f + __expf(-v2)) * v3;
                Ch[(long long)r * ldc + (cn >> 1)]       = __float2half(o0);
                Ch[(long long)(r + 8) * ldc + (cn >> 1)] = __float2half(o1);
                continue;
            }
            if (ROPE) {
                if (cn < HD + KVD) {
                    const int pidx = (cn & (DH - 1)) >> 1;
                    const float2 t0 = g_rope[(r & (S_ - 1)) * (DH/2) + pidx];
                    const float2 t1 = g_rope[((r + 8) & (S_ - 1)) * (DH/2) + pidx];
                    float nv0 = t0.x * v0 - t0.y * v1;
                    float nv1 = t0.y * v0 + t0.x * v1;
                    float nv2 = t1.x * v2 - t1.y * v3;
                    float nv3 = t1.y * v2 + t1.x * v3;
                    v0 = nv0; v1 = nv1; v2 = nv2; v3 = nv3;
                }
            }
            if (resid) {
                const float* rr0 = &resid[(long long)r * ldr + cn];
                const float* rr1 = &resid[(long long)(r + 8) * ldr + cn];
                v0 += rr0[0]; v1 += rr0[1]; v2 += rr1[0]; v3 += rr1[1];
            }
            if (OUTH) {
                *reinterpret_cast<__half2*>(&Ch[(long long)r * ldc + cn]) =
                    __floats2half2_rn(v0, v1);
                *reinterpret_cast<__half2*>(&Ch[(long long)(r + 8) * ldc + cn]) =
                    __floats2half2_rn(v2, v3);
            } else {
                *reinterpret_cast<float2*>(&Cf[(long long)r * ldc + cn]) = make_float2(v0, v1);
                *reinterpret_cast<float2*>(&Cf[(long long)(r + 8) * ldc + cn]) = make_float2(v2, v3);
            }
        }
    }
}

// ---------------- FlashAttention-2 over packed qkv [T, 3072] ----------------
__global__ __launch_bounds__(256, 1)
void flash_k(const __half* __restrict__ qkv, const float* __restrict__ mask,
             __half* __restrict__ O) {
    extern __shared__ char smraw[];
    float* smask = (float*)smraw;
    const unsigned suKV = (unsigned)__cvta_generic_to_shared(smraw + 4096);

    const int tid = threadIdx.x, lane = tid & 31, warp = tid >> 5;
    const int s0 = blockIdx.x * 128;
    const int h = blockIdx.y, b = blockIdx.z;
    const int kvh = h / (NH / NKV);

    const __half* Qg = qkv + ((long long)(b * S_ + s0)) * QKVN + h * DH;
    const __half* Kg = qkv + ((long long)b * S_) * QKVN + HD + kvh * DH;
    const __half* Vg = qkv + ((long long)b * S_) * QKVN + HD + KVD + kvh * DH;

    for (int i = tid; i < S_ / 4; i += 256)
        *(float4*)&smask[i * 4] = *(const float4*)&mask[b * S_ + i * 4];

    #pragma unroll
    for (int i = 0; i < 8; i++) {
        int idx = tid + 256 * i;
        int row = idx >> 4, col = (idx & 15) * 8;
        cpa16(suKV + (unsigned)(row * 136 + col) * 2, Qg + (long long)row * QKVN + col);
    }
    cpa_commit();
    cpa_wait<0>();
    __syncthreads();

    unsigned af[8][4];
    {
        const int ar = warp * 16 + (lane & 15);
        const int ac = (lane >> 4) * 8;
        #pragma unroll
        for (int t = 0; t < 8; t++)
            ldsm4(af[t][0], af[t][1], af[t][2], af[t][3],
                  suKV + (unsigned)(ar * 136 + t * 16 + ac) * 2);
    }
    __syncthreads();

    auto load_kv = [&](int tile, int stage) {
        const int kv0 = tile * 64;
        const unsigned kb = suKV + (unsigned)(stage * 17408) * 2;
        const unsigned vbx = kb + 8704u * 2;
        #pragma unroll
        for (int i = 0; i < 4; i++) {
            int idx = tid + 256 * i;
            int row = idx >> 4, col = (idx & 15) * 8;
            cpa16(kb + (unsigned)(row * 136 + col) * 2,
                  Kg + (long long)(kv0 + row) * QKVN + col);
            cpa16(vbx + (unsigned)(row * 136 + col) * 2,
                  Vg + (long long)(kv0 + row) * QKVN + col);
        }
    };

    load_kv(0, 0); cpa_commit();
    load_kv(1, 1); cpa_commit();

    float oacc[16][4];
    #pragma unroll
    for (int d = 0; d < 16; d++)
        #pragma unroll
        for (int q = 0; q < 4; q++) oacc[d][q] = 0.f;

    float m0r = -INFINITY, m1r = -INFINITY, l0r = 0.f, l1r = 0.f;
    const int r0 = warp * 16 + (lane >> 2);
    const float mq0 = smask[s0 + r0];
    const float mq1 = smask[s0 + r0 + 8];
    const float scale = 0.08838834764831845f;

    for (int t = 0; t < 16; t++) {
        cpa_wait<1>();
        __syncthreads();
        const int stage = t & 1;
        const unsigned kb = suKV + (unsigned)(stage * 17408) * 2;
        const unsigned vbx = kb + 8704u * 2;

        float sacc[8][4];
        #pragma unroll
        for (int j = 0; j < 8; j++)
            #pragma unroll
            for (int q = 0; q < 4; q++) sacc[j][q] = 0.f;

        #pragma unroll
        for (int ks = 0; ks < 8; ks++) {
            unsigned bf[8][2];
            #pragma unroll
            for (int g = 0; g < 4; g++) {
                const int br = g * 16 + (lane >> 4) * 8 + (lane & 7);
                const int bc = ks * 16 + ((lane >> 3) & 1) * 8;
                ldsm4(bf[g*2][0], bf[g*2][1], bf[g*2+1][0], bf[g*2+1][1],
                      kb + (unsigned)(br * 136 + bc) * 2);
            }
            #pragma unroll
            for (int j = 0; j < 8; j++)
                mma16816(sacc[j], af[ks], bf[j]);
        }

        const int kvb = t * 64;
        float t0 = -INFINITY, t1 = -INFINITY;
        #pragma unroll
        for (int j = 0; j < 8; j++) {
            const int c = kvb + j * 8 + (lane & 3) * 2;
            const float mk0 = smask[c], mk1 = smask[c + 1];
            sacc[j][0] = (mq0 * mk0 == 0.f) ? -1e30f : sacc[j][0] * scale;
            sacc[j][1] = (mq0 * mk1 == 0.f) ? -1e30f : sacc[j][1] * scale;
            sacc[j][2] = (mq1 * mk0 == 0.f) ? -1e30f : sacc[j][2] * scale;
            sacc[j][3] = (mq1 * mk1 == 0.f) ? -1e30f : sacc[j][3] * scale;
            t0 = fmaxf(t0, fmaxf(sacc[j][0], sacc[j][1]));
            t1 = fmaxf(t1, fmaxf(sacc[j][2], sacc[j][3]));
        }
        t0 = fmaxf(t0, __shfl_xor_sync(0xffffffffu, t0, 1));
        t0 = fmaxf(t0, __shfl_xor_sync(0xffffffffu, t0, 2));
        t1 = fmaxf(t1, __shfl_xor_sync(0xffffffffu, t1, 1));
        t1 = fmaxf(t1, __shfl_xor_sync(0xffffffffu, t1, 2));

        const float mn0 = fmaxf(m0r, t0), mn1 = fmaxf(m1r, t1);
        const float a0 = __expf(m0r - mn0), a1 = __expf(m1r - mn1);
        m0r = mn0; m1r = mn1;

        float s0s = 0.f, s1s = 0.f;
        #pragma unroll
        for (int j = 0; j < 8; j++) {
            sacc[j][0] = __expf(sacc[j][0] - mn0);
            sacc[j][1] = __expf(sacc[j][1] - mn0);
            sacc[j][2] = __expf(sacc[j][2] - mn1);
            sacc[j][3] = __expf(sacc[j][3] - mn1);
            s0s += sacc[j][0] + sacc[j][1];
            s1s += sacc[j][2] + sacc[j][3];
        }
        s0s += __shfl_xor_sync(0xffffffffu, s0s, 1);
        s0s += __shfl_xor_sync(0xffffffffu, s0s, 2);
        s1s += __shfl_xor_sync(0xffffffffu, s1s, 1);
        s1s += __shfl_xor_sync(0xffffffffu, s1s, 2);
        l0r = l0r * a0 + s0s;
        l1r = l1r * a1 + s1s;

        #pragma unroll
        for (int d = 0; d < 16; d++) {
            oacc[d][0] *= a0; oacc[d][1] *= a0;
            oacc[d][2] *= a1; oacc[d][3] *= a1;
        }

        unsigned pa[4][4];
        #pragma unroll
        for (int kk = 0; kk < 4; kk++) {
            pa[kk][0] = packh2(sacc[2*kk][0],   sacc[2*kk][1]);
            pa[kk][1] = packh2(sacc[2*kk][2],   sacc[2*kk][3]);
            pa[kk][2] = packh2(sacc[2*kk+1][0], sacc[2*kk+1][1]);
            pa[kk][3] = packh2(sacc[2*kk+1][2], sacc[2*kk+1][3]);
        }

        #pragma unroll
        for (int kk = 0; kk < 4; kk++) {
            const int kr = kk * 16 + (lane & 15);
            const int ncl = (lane >> 4) * 8;
            unsigned vbf[16][2];
            #pragma unroll
            for (int dp = 0; dp < 8; dp++)
                ldsm4t(vbf[dp*2][0], vbf[dp*2][1], vbf[dp*2+1][0], vbf[dp*2+1][1],
                       vbx + (unsigned)(kr * 136 + dp * 16 + ncl) * 2);
            #pragma unroll
            for (int d = 0; d < 16; d++)
                mma16816(oacc[d], pa[kk], vbf[d]);
        }

        __syncthreads();
        if (t + 2 < 16) load_kv(t + 2, stage);
        cpa_commit();
    }

    const float i0 = 1.f / l0r, i1 = 1.f / l1r;
    __half* Og = O + ((long long)(b * S_ + s0 + r0)) * HD + h * DH;
    #pragma unroll
    for (int d = 0; d < 16; d++) {
        const int col = d * 8 + (lane & 3) * 2;
        *reinterpret_cast<__half2*>(&Og[col]) =
            __floats2half2_rn(oacc[d][0] * i0, oacc[d][1] * i0);
        *reinterpret_cast<__half2*>(&Og[(long long)8 * HD + col]) =
            __floats2half2_rn(oacc[d][2] * i1, oacc[d][3] * i1);
    }
}

// ---------------- elementwise kernels ---------------------------------------
__global__ void rope_tab_k() {
    int idx = blockIdx.x * blockDim.x + threadIdx.x;   // over S_ * DH/2
    if (idx >= S_ * (DH/2)) return;
    int s = idx >> 6, p = idx & 63;
    float inv = powf(10000.0f, -(float)(2 * p) / (float)DH);
    float ang = (float)s * inv;
    float sn, cs; sincosf(ang, &sn, &cs);
    g_rope[idx] = make_float2(cs, sn);
}

// weight convert: segments Q | K | V | O | GATE+UP(interleaved) | DOWN
#define SEG_BIG  (HD*HD)      // 4M
#define SEG_SM   (HD*KVD)     // 1M
__global__ void f2h_all_k(const float* __restrict__ wq, const float* __restrict__ wk,
                          const float* __restrict__ wv, const float* __restrict__ wo,
                          const float* __restrict__ wg, const float* __restrict__ wu,
                          const float* __restrict__ wd,
                          __half* __restrict__ wqkv, __half* __restrict__ oo,
                          __half* __restrict__ wgu, __half* __restrict__ od) {
    long long i = ((long long)blockIdx.x * blockDim.x + threadIdx.x) * 8;
    const long long big = SEG_BIG, sg = SEG_SM;
    if (i >= big + 2*sg + big && i < big + 2*sg + 2*big) {
        long long off = i - big - 2*sg - big;
        long long row = off >> 11, j = off & 2047;
        float4 gA = *reinterpret_cast<const float4*>(&wg[off]);
        float4 gB = *reinterpret_cast<const float4*>(&wg[off + 4]);
        float4 uA = *reinterpret_cast<const float4*>(&wu[off]);
        float4 uB = *reinterpret_cast<const float4*>(&wu[off + 4]);
        __half* dst = wgu + row * GUN + 2 * j;
        uint4 o0, o1;
        o0.x = packh2(gA.x, uA.x); o0.y = packh2(gA.y, uA.y);
        o0.z = packh2(gA.z, uA.z); o0.w = packh2(gA.w, uA.w);
        o1.x = packh2(gB.x, uB.x); o1.y = packh2(gB.y, uB.y);
        o1.z = packh2(gB.z, uB.z); o1.w = packh2(gB.w, uB.w);
        *reinterpret_cast<uint4*>(dst)     = o0;
        *reinterpret_cast<uint4*>(dst + 8) = o1;
        return;
    }
    const float* src; __half* dst; long long off, doff;
    if (i < big) {
        src = wq; off = i;
        doff = (off >> 11) * QKVN + (off & 2047);
        dst = wqkv;
    } else if (i < big + sg) {
        src = wk; off = i - big;
        doff = (off >> 9) * QKVN + HD + (off & 511);
        dst = wqkv;
    } else if (i < big + 2*sg) {
        src = wv; off = i - big - sg;
        doff = (off >> 9) * QKVN + HD + KVD + (off & 511);
        dst = wqkv;
    } else if (i < big + 2*sg + big) {
        src = wo; off = i - big - 2*sg; dst = oo; doff = off;
    } else {
        src = wd; off = i - big - 2*sg - 2*big; dst = od; doff = off;
    }
    float4 v0 = *reinterpret_cast<const float4*>(&src[off]);
    float4 v1 = *reinterpret_cast<const float4*>(&src[off + 4]);
    uint4 u;
    u.x = packh2(v0.x, v0.y); u.y = packh2(v0.z, v0.w);
    u.z = packh2(v1.x, v1.y); u.w = packh2(v1.z, v1.w);
    *reinterpret_cast<uint4*>(&dst[doff]) = u;
}

__global__ void bias_gu_k(const float* __restrict__ bg, const float* __restrict__ bu) {
    int j = blockIdx.x * blockDim.x + threadIdx.x;
    if (j >= HD) return;
    g_bgu[2*j]   = bg[j];
    g_bgu[2*j+1] = bu[j];
}

// fast RMSNorm: single pass, float4 loads, warp-shuffle reduction, uint4 store
__global__ void rmsnorm_h(const float* __restrict__ x, const float* __restrict__ g,
                          __half* __restrict__ o) {
    __shared__ float swarp[8];
    const int row = blockIdx.x, tid = threadIdx.x;
    const int lane = tid & 31, warp = tid >> 5;
    const float* xr = x + (long long)row * HD + tid * 8;

    float4 a = *reinterpret_cast<const float4*>(xr);
    float4 b = *reinterpret_cast<const float4*>(xr + 4);
    float s = a.x*a.x + a.y*a.y + a.z*a.z + a.w*a.w
            + b.x*b.x + b.y*b.y + b.z*b.z + b.w*b.w;
    #pragma unroll
    for (int st = 16; st > 0; st >>= 1)
        s += __shfl_xor_sync(0xffffffffu, s, st);
    if (lane == 0) swarp[warp] = s;
    __syncthreads();
    if (warp == 0) {
        float t = (lane < 8) ? swarp[lane] : 0.f;
        #pragma unroll
        for (int st = 4; st > 0; st >>= 1)
            t += __shfl_xor_sync(0xffffffffu, t, st);
        if (lane == 0) swarp[0] = t;
    }
    __syncthreads();
    const float inv = rsqrtf(swarp[0] / (float)HD + 1e-8f);

    const float* gr = g + tid * 8;
    float4 ga = *reinterpret_cast<const float4*>(gr);
    float4 gb = *reinterpret_cast<const float4*>(gr + 4);
    uint4 u;
    u.x = packh2(a.x * inv * ga.x, a.y * inv * ga.y);
    u.y = packh2(a.z * inv * ga.z, a.w * inv * ga.w);
    u.z = packh2(b.x * inv * gb.x, b.y * inv * gb.y);
    u.w = packh2(b.z * inv * gb.z, b.w * inv * gb.w);
    *reinterpret_cast<uint4*>(o + (long long)row * HD + tid * 8) = u;
}

// ---------------- host side --------------------------------------------------
static const int SMEM_G  = 3 * (128 * 72 + 64 * 136) * 2;   // 107520
static const int SMEM_FA = 4096 + 2 * 2 * 8704 * 2;         // 73728

template<bool OUTH, bool SILU, bool ROPE>
static void launch_gemm(const __half* A, const __half* B,
                        float* Cf, __half* Ch,
                        const float* bias, const float* resid,
                        int M, int N, int K, int lda, int ldb, int ldc, int ldr,
                        float scale) {
    dim3 grid(N / 128, M / 128), block(256);
    cudaFuncSetAttribute(hgemm_k<OUTH, SILU, ROPE>,
                         cudaFuncAttributeMaxDynamicSharedMemorySize, SMEM_G);
    hgemm_k<OUTH, SILU, ROPE><<<grid, block, SMEM_G>>>(
        A, B, Cf, Ch, bias, resid, M, N, K, lda, ldb, ldc, ldr, scale);
}

extern "C" void kernel_launch(void* const* d_in, const int* in_sizes, int n_in,
                              void* d_out, int out_size) {
    const float* enc    = (const float*)d_in[0];
    const float* mask   = (const float*)d_in[1];
    const float* gin    = (const float*)d_in[4];
    const float* gffn   = (const float*)d_in[5];
    const float* w_q    = (const float*)d_in[6];
    const float* b_q    = (const float*)d_in[7];
    const float* w_k    = (const float*)d_in[8];
    const float* b_k    = (const float*)d_in[9];
    const float* w_v    = (const float*)d_in[10];
    const float* b_v    = (const float*)d_in[11];
    const float* w_o    = (const float*)d_in[12];
    const float* b_o    = (const float*)d_in[13];
    const float* w_gate = (const float*)d_in[14];
    const float* b_gate = (const float*)d_in[15];
    const float* w_up   = (const float*)d_in[16];
    const float* b_up   = (const float*)d_in[17];
    const float* w_down = (const float*)d_in[18];
    const float* b_down = (const float*)d_in[19];
    float* out = (float*)d_out;

    float *ao, *bqkv, *bgu;
    __half *wqkv, *woh, *wgu, *wdh;
    __half *xnh, *qkv, *cxh, *hh, *guh;
    cudaGetSymbolAddress((void**)&ao,   g_ao);
    cudaGetSymbolAddress((void**)&bqkv, g_bqkv);
    cudaGetSymbolAddress((void**)&bgu,  g_bgu);
    cudaGetSymbolAddress((void**)&wqkv, g_wqkv);
    cudaGetSymbolAddress((void**)&woh,  g_woh);
    cudaGetSymbolAddress((void**)&wgu,  g_wgu);
    cudaGetSymbolAddress((void**)&wdh,  g_wdh);
    cudaGetSymbolAddress((void**)&xnh,  g_xnh);
    cudaGetSymbolAddress((void**)&qkv,  g_qkv);
    cudaGetSymbolAddress((void**)&cxh,  g_cxh);
    cudaGetSymbolAddress((void**)&hh,   g_hh);
    cudaGetSymbolAddress((void**)&guh,  g_guh);

    // 0) rope table + weights -> fp16 (q/k/v packed, gate/up interleaved)
    rope_tab_k<<<(S_ * (DH/2)) / 256, 256>>>();
    {
        long long tot = 4LL * SEG_BIG + 2LL * SEG_SM;
        f2h_all_k<<<(unsigned)(tot / 2048), 256>>>(
            w_q, w_k, w_v, w_o, w_gate, w_up, w_down,
            wqkv, woh, wgu, wdh);
        bias_gu_k<<<HD / 256, 256>>>(b_gate, b_up);
        cudaMemcpyAsync(bqkv,            b_q, HD  * sizeof(float), cudaMemcpyDeviceToDevice);
        cudaMemcpyAsync(bqkv + HD,       b_k, KVD * sizeof(float), cudaMemcpyDeviceToDevice);
        cudaMemcpyAsync(bqkv + HD + KVD, b_v, KVD * sizeof(float), cudaMemcpyDeviceToDevice);
    }

    // 1) x = RMSNorm(enc) -> fp16
    rmsnorm_h<<<T_, 256>>>(enc, gin, xnh);

    // 2) fused QKV projection with RoPE in epilogue -> packed [T, 3072] fp16
    launch_gemm<true, false, true>(xnh, wqkv, nullptr, qkv, bqkv, nullptr,
                                   T_, QKVN, HD, HD, QKVN, QKVN, 0, 1.0f);

    // 3-6) fused flash attention -> ctx fp16 [B,S,HD]
    {
        cudaFuncSetAttribute(flash_k, cudaFuncAttributeMaxDynamicSharedMemorySize, SMEM_FA);
        dim3 grid(S_ / 128, NH, B_);
        flash_k<<<grid, 256, SMEM_FA>>>(qkv, mask, cxh);
    }

    // 7) attn_out = enc + ctx @ w_o + b_o   (fp32)
    launch_gemm<false, false, false>(cxh, woh, ao, nullptr, b_o, enc,
                                     T_, HD, HD, HD, HD, HD, HD, 1.0f);

    // 8) h = RMSNorm(attn_out) -> fp16
    rmsnorm_h<<<T_, 256>>>(ao, gffn, hh);

    // 9) fused gate|up GEMM with SiLU epilogue -> guh fp16 [T, HD]
    launch_gemm<true, true, false>(hh, wgu, nullptr, guh, bgu, nullptr,
                                   T_, GUN, HD, HD, GUN, HD, 0, 1.0f);

    // 10) out = attn_out + gu @ w_down + b_down
    launch_gemm<false, false, false>(guh, wdh, out, nullptr, b_down, ao,
                                     T_, HD, HD, HD, HD, HD, HD, 1.0f);
}

// round 14
// speedup vs baseline: 1.1287x; 1.0217x over previous
#include <cuda_runtime.h>
#include <cuda_fp16.h>
#include <cstdint>
#include <math.h>

// ---------------- problem constants ----------------
#define B_   4
#define S_   1024
#define HD   2048
#define NH   16
#define NKV  4
#define DH   128
#define T_   (B_*S_)        // 4096
#define KVD  (NKV*DH)       // 512
#define QKVN (HD + 2*KVD)   // 3072 packed q|k|v columns
#define GUN  (2*HD)         // 4096 interleaved gate|up columns

// ---------------- scratch (device globals) ----------
__device__ float  g_ao  [(size_t)T_*HD];
__device__ float  g_bqkv[QKVN];
__device__ float  g_bgu [GUN];
__device__ float2 g_rope[S_ * (DH/2)];              // [s][d/2] -> (cos, sin)
__device__ __half g_wqkv[(size_t)HD*QKVN];
__device__ __half g_woh[(size_t)HD*HD];
__device__ __half g_wgu[(size_t)HD*GUN];
__device__ __half g_wdh[(size_t)HD*HD];
__device__ __half g_xnh[(size_t)T_*HD];
__device__ __half g_qkv[(size_t)T_*QKVN];
__device__ __half g_cxh[(size_t)T_*HD];
__device__ __half g_hh [(size_t)T_*HD];
__device__ __half g_guh[(size_t)T_*HD];

// ---------------- ptx helpers -----------------------
__device__ __forceinline__ void cpa16(unsigned int dst, const void* src) {
    asm volatile("cp.async.cg.shared.global [%0], [%1], 16;\n" :: "r"(dst), "l"(src));
}
__device__ __forceinline__ void cpa_commit() {
    asm volatile("cp.async.commit_group;\n");
}
template<int N>
__device__ __forceinline__ void cpa_wait() {
    asm volatile("cp.async.wait_group %0;\n" :: "n"(N));
}
__device__ __forceinline__ void ldsm4(unsigned &r0, unsigned &r1, unsigned &r2, unsigned &r3,
                                      unsigned int addr) {
    asm volatile("ldmatrix.sync.aligned.m8n8.x4.shared.b16 {%0,%1,%2,%3}, [%4];\n"
                 : "=r"(r0), "=r"(r1), "=r"(r2), "=r"(r3) : "r"(addr));
}
__device__ __forceinline__ void ldsm4t(unsigned &r0, unsigned &r1, unsigned &r2, unsigned &r3,
                                       unsigned int addr) {
    asm volatile("ldmatrix.sync.aligned.m8n8.x4.trans.shared.b16 {%0,%1,%2,%3}, [%4];\n"
                 : "=r"(r0), "=r"(r1), "=r"(r2), "=r"(r3) : "r"(addr));
}
__device__ __forceinline__ void mma16816(float c[4], const unsigned a[4], const unsigned b[2]) {
    asm volatile(
        "mma.sync.aligned.m16n8k16.row.col.f32.f16.f16.f32 "
        "{%0,%1,%2,%3},{%4,%5,%6,%7},{%8,%9},{%0,%1,%2,%3};\n"
        : "+f"(c[0]), "+f"(c[1]), "+f"(c[2]), "+f"(c[3])
        : "r"(a[0]), "r"(a[1]), "r"(a[2]), "r"(a[3]), "r"(b[0]), "r"(b[1]));
}
__device__ __forceinline__ unsigned packh2(float a, float b) {
    __half2 h = __floats2half2_rn(a, b);
    return *reinterpret_cast<unsigned*>(&h);
}

// ---------------- fp16 GEMM, 128x128 tile, BK=64, 3-stage (proven) ---------
template<bool OUTH, bool SILU, bool ROPE>
__global__ __launch_bounds__(256, 2)
void hgemm_k(const __half* __restrict__ A, const __half* __restrict__ B,
             float* __restrict__ Cf, __half* __restrict__ Ch,
             const float* __restrict__ bias, const float* __restrict__ resid,
             int M, int N, int K, int lda, int ldb, int ldc, int ldr,
             float scale) {
    constexpr int ASTG = 128 * 72;
    constexpr int BSTG = 64 * 136;
    constexpr int STG  = ASTG + BSTG;
    extern __shared__ __half sm[];

    const int tid = threadIdx.x, lane = tid & 31, warp = tid >> 5;
    const int warpM = warp >> 2, warpN = warp & 3;
    const int m0 = blockIdx.y * 128, n0 = blockIdx.x * 128;

    const unsigned su = (unsigned)__cvta_generic_to_shared(sm);

    const int arow = tid >> 3, acc8 = (tid & 7) * 8;
    const int brow = tid >> 4, bcc8 = (tid & 15) * 8;

    auto load_stage = [&](int kt, int buf) {
        const int k0 = kt << 6;
        const unsigned sa = su + (unsigned)(buf * STG) * 2;
        const unsigned sb = sa + (unsigned)ASTG * 2;
        #pragma unroll
        for (int i = 0; i < 4; i++) {
            int row = arow + i * 32;
            cpa16(sa + (unsigned)(row * 72 + acc8) * 2,
                  A + (long long)(m0 + row) * lda + k0 + acc8);
        }
        #pragma unroll
        for (int i = 0; i < 4; i++) {
            int kr = brow + i * 16;
            cpa16(sb + (unsigned)(kr * 136 + bcc8) * 2,
                  B + (long long)(k0 + kr) * ldb + n0 + bcc8);
        }
    };

    float acc[4][4][4];
    #pragma unroll
    for (int i = 0; i < 4; i++)
        #pragma unroll
        for (int j = 0; j < 4; j++)
            #pragma unroll
            for (int q = 0; q < 4; q++) acc[i][j][q] = 0.f;

    const int ktiles = K >> 6;
    load_stage(0, 0); cpa_commit();
    if (ktiles > 1) load_stage(1, 1);
    cpa_commit();

    int buf = 0;
    for (int kt = 0; kt < ktiles; kt++) {
        cpa_wait<1>();
        __syncthreads();

        {
            int pf = kt + 2;
            if (pf < ktiles) {
                int pbuf = buf + 2; if (pbuf >= 3) pbuf -= 3;
                load_stage(pf, pbuf);
            }
            cpa_commit();
        }

        const unsigned sa = su + (unsigned)(buf * STG) * 2;
        const unsigned sb = sa + (unsigned)ASTG * 2;

        #pragma unroll
        for (int kk = 0; kk < 4; kk++) {
            unsigned af[4][4], bf[4][2];
            const int ar = warpM * 64 + (lane & 15);
            const int ac = kk * 16 + (lane >> 4) * 8;
            #pragma unroll
            for (int i = 0; i < 4; i++)
                ldsm4(af[i][0], af[i][1], af[i][2], af[i][3],
                      sa + (unsigned)((ar + i * 16) * 72 + ac) * 2);

            const int kr = kk * 16 + (lane & 15);
            const int ncl = (lane >> 4) * 8;
            #pragma unroll
            for (int jj = 0; jj < 2; jj++) {
                const int nb = warpN * 32 + jj * 16;
                ldsm4t(bf[jj*2][0], bf[jj*2][1], bf[jj*2+1][0], bf[jj*2+1][1],
                       sb + (unsigned)(kr * 136 + nb + ncl) * 2);
            }
            #pragma unroll
            for (int i = 0; i < 4; i++)
                #pragma unroll
                for (int j = 0; j < 4; j++)
                    mma16816(acc[i][j], af[i], bf[j]);
        }
        buf++; if (buf >= 3) buf -= 3;
    }

    #pragma unroll
    for (int i = 0; i < 4; i++) {
        const int r = m0 + warpM * 64 + i * 16 + (lane >> 2);
        #pragma unroll
        for (int j = 0; j < 4; j++) {
            const int cn = n0 + warpN * 32 + j * 8 + (lane & 3) * 2;
            float b0 = 0.f, b1 = 0.f;
            if (bias) { b0 = bias[cn]; b1 = bias[cn + 1]; }
            float v0 = acc[i][j][0] * scale + b0;
            float v1 = acc[i][j][1] * scale + b1;
            float v2 = acc[i][j][2] * scale + b0;
            float v3 = acc[i][j][3] * scale + b1;
            if (SILU) {
                float o0 = v0 / (1.0f + __expf(-v0)) * v1;
                float o1 = v2 / (1.0f + __expf(-v2)) * v3;
                Ch[(long long)r * ldc + (cn >> 1)]       = __float2half(o0);
                Ch[(long long)(r + 8) * ldc + (cn >> 1)] = __float2half(o1);
                continue;
            }
            if (ROPE) {
                if (cn < HD + KVD) {
                    const int pidx = (cn & (DH - 1)) >> 1;
                    const float2 t0 = g_rope[(r & (S_ - 1)) * (DH/2) + pidx];
                    const float2 t1 = g_rope[((r + 8) & (S_ - 1)) * (DH/2) + pidx];
                    float nv0 = t0.x * v0 - t0.y * v1;
                    float nv1 = t0.y * v0 + t0.x * v1;
                    float nv2 = t1.x * v2 - t1.y * v3;
                    float nv3 = t1.y * v2 + t1.x * v3;
                    v0 = nv0; v1 = nv1; v2 = nv2; v3 = nv3;
                }
            }
            if (resid) {
                const float* rr0 = &resid[(long long)r * ldr + cn];
                const float* rr1 = &resid[(long long)(r + 8) * ldr + cn];
                v0 += rr0[0]; v1 += rr0[1]; v2 += rr1[0]; v3 += rr1[1];
            }
            if (OUTH) {
                *reinterpret_cast<__half2*>(&Ch[(long long)r * ldc + cn]) =
                    __floats2half2_rn(v0, v1);
                *reinterpret_cast<__half2*>(&Ch[(long long)(r + 8) * ldc + cn]) =
                    __floats2half2_rn(v2, v3);
            } else {
                *reinterpret_cast<float2*>(&Cf[(long long)r * ldc + cn]) = make_float2(v0, v1);
                *reinterpret_cast<float2*>(&Cf[(long long)(r + 8) * ldc + cn]) = make_float2(v2, v3);
            }
        }
    }
}

// ---------------- FlashAttention-2: 64-row q-tiles, 128 thr, 2 CTAs/SM ------
__global__ __launch_bounds__(128, 2)
void flash_k(const __half* __restrict__ qkv, const float* __restrict__ mask,
             __half* __restrict__ O) {
    extern __shared__ char smraw[];
    float* smask = (float*)smraw;
    const unsigned suKV = (unsigned)__cvta_generic_to_shared(smraw + 4096);

    const int tid = threadIdx.x, lane = tid & 31, warp = tid >> 5;   // 4 warps
    const int s0 = blockIdx.x * 64;
    const int h = blockIdx.y, b = blockIdx.z;
    const int kvh = h / (NH / NKV);

    const __half* Qg = qkv + ((long long)(b * S_ + s0)) * QKVN + h * DH;
    const __half* Kg = qkv + ((long long)b * S_) * QKVN + HD + kvh * DH;
    const __half* Vg = qkv + ((long long)b * S_) * QKVN + HD + KVD + kvh * DH;

    for (int i = tid; i < S_ / 4; i += 128)
        *(float4*)&smask[i * 4] = *(const float4*)&mask[b * S_ + i * 4];

    // stage Q (64x128) into KV smem area (reused afterwards)
    #pragma unroll
    for (int i = 0; i < 8; i++) {
        int idx = tid + 128 * i;                 // 0..1023
        int row = idx >> 4, col = (idx & 15) * 8;
        cpa16(suKV + (unsigned)(row * 136 + col) * 2, Qg + (long long)row * QKVN + col);
    }
    cpa_commit();
    cpa_wait<0>();
    __syncthreads();

    unsigned af[8][4];
    {
        const int ar = warp * 16 + (lane & 15);
        const int ac = (lane >> 4) * 8;
        #pragma unroll
        for (int t = 0; t < 8; t++)
            ldsm4(af[t][0], af[t][1], af[t][2], af[t][3],
                  suKV + (unsigned)(ar * 136 + t * 16 + ac) * 2);
    }
    __syncthreads();

    auto load_kv = [&](int tile, int stage) {
        const int kv0 = tile * 64;
        const unsigned kb = suKV + (unsigned)(stage * 17408) * 2;
        const unsigned vbx = kb + 8704u * 2;
        #pragma unroll
        for (int i = 0; i < 8; i++) {
            int idx = tid + 128 * i;
            int row = idx >> 4, col = (idx & 15) * 8;
            cpa16(kb + (unsigned)(row * 136 + col) * 2,
                  Kg + (long long)(kv0 + row) * QKVN + col);
            cpa16(vbx + (unsigned)(row * 136 + col) * 2,
                  Vg + (long long)(kv0 + row) * QKVN + col);
        }
    };

    load_kv(0, 0); cpa_commit();
    load_kv(1, 1); cpa_commit();

    float oacc[16][4];
    #pragma unroll
    for (int d = 0; d < 16; d++)
        #pragma unroll
        for (int q = 0; q < 4; q++) oacc[d][q] = 0.f;

    float m0r = -INFINITY, m1r = -INFINITY, l0r = 0.f, l1r = 0.f;
    const int r0 = warp * 16 + (lane >> 2);
    const float mq0 = smask[s0 + r0];
    const float mq1 = smask[s0 + r0 + 8];
    const float scale = 0.08838834764831845f;

    for (int t = 0; t < 16; t++) {
        cpa_wait<1>();
        __syncthreads();
        const int stage = t & 1;
        const unsigned kb = suKV + (unsigned)(stage * 17408) * 2;
        const unsigned vbx = kb + 8704u * 2;

        float sacc[8][4];
        #pragma unroll
        for (int j = 0; j < 8; j++)
            #pragma unroll
            for (int q = 0; q < 4; q++) sacc[j][q] = 0.f;

        #pragma unroll
        for (int ks = 0; ks < 8; ks++) {
            unsigned bf[8][2];
            #pragma unroll
            for (int g = 0; g < 4; g++) {
                const int br = g * 16 + (lane >> 4) * 8 + (lane & 7);
                const int bc = ks * 16 + ((lane >> 3) & 1) * 8;
                ldsm4(bf[g*2][0], bf[g*2][1], bf[g*2+1][0], bf[g*2+1][1],
                      kb + (unsigned)(br * 136 + bc) * 2);
            }
            #pragma unroll
            for (int j = 0; j < 8; j++)
                mma16816(sacc[j], af[ks], bf[j]);
        }

        const int kvb = t * 64;
        float t0 = -INFINITY, t1 = -INFINITY;
        #pragma unroll
        for (int j = 0; j < 8; j++) {
            const int c = kvb + j * 8 + (lane & 3) * 2;
            const float mk0 = smask[c], mk1 = smask[c + 1];
            sacc[j][0] = (mq0 * mk0 == 0.f) ? -1e30f : sacc[j][0] * scale;
            sacc[j][1] = (mq0 * mk1 == 0.f) ? -1e30f : sacc[j][1] * scale;
            sacc[j][2] = (mq1 * mk0 == 0.f) ? -1e30f : sacc[j][2] * scale;
            sacc[j][3] = (mq1 * mk1 == 0.f) ? -1e30f : sacc[j][3] * scale;
            t0 = fmaxf(t0, fmaxf(sacc[j][0], sacc[j][1]));
            t1 = fmaxf(t1, fmaxf(sacc[j][2], sacc[j][3]));
        }
        t0 = fmaxf(t0, __shfl_xor_sync(0xffffffffu, t0, 1));
        t0 = fmaxf(t0, __shfl_xor_sync(0xffffffffu, t0, 2));
        t1 = fmaxf(t1, __shfl_xor_sync(0xffffffffu, t1, 1));
        t1 = fmaxf(t1, __shfl_xor_sync(0xffffffffu, t1, 2));

        const float mn0 = fmaxf(m0r, t0), mn1 = fmaxf(m1r, t1);
        const float a0 = __expf(m0r - mn0), a1 = __expf(m1r - mn1);
        m0r = mn0; m1r = mn1;

        float s0s = 0.f, s1s = 0.f;
        #pragma unroll
        for (int j = 0; j < 8; j++) {
            sacc[j][0] = __expf(sacc[j][0] - mn0);
            sacc[j][1] = __expf(sacc[j][1] - mn0);
            sacc[j][2] = __expf(sacc[j][2] - mn1);
            sacc[j][3] = __expf(sacc[j][3] - mn1);
            s0s += sacc[j][0] + sacc[j][1];
            s1s += sacc[j][2] + sacc[j][3];
        }
        s0s += __shfl_xor_sync(0xffffffffu, s0s, 1);
        s0s += __shfl_xor_sync(0xffffffffu, s0s, 2);
        s1s += __shfl_xor_sync(0xffffffffu, s1s, 1);
        s1s += __shfl_xor_sync(0xffffffffu, s1s, 2);
        l0r = l0r * a0 + s0s;
        l1r = l1r * a1 + s1s;

        #pragma unroll
        for (int d = 0; d < 16; d++) {
            oacc[d][0] *= a0; oacc[d][1] *= a0;
            oacc[d][2] *= a1; oacc[d][3] *= a1;
        }

        unsigned pa[4][4];
        #pragma unroll
        for (int kk = 0; kk < 4; kk++) {
            pa[kk][0] = packh2(sacc[2*kk][0],   sacc[2*kk][1]);
            pa[kk][1] = packh2(sacc[2*kk][2],   sacc[2*kk][3]);
            pa[kk][2] = packh2(sacc[2*kk+1][0], sacc[2*kk+1][1]);
            pa[kk][3] = packh2(sacc[2*kk+1][2], sacc[2*kk+1][3]);
        }

        #pragma unroll
        for (int kk = 0; kk < 4; kk++) {
            const int kr = kk * 16 + (lane & 15);
            const int ncl = (lane >> 4) * 8;
            unsigned vbf[16][2];
            #pragma unroll
            for (int dp = 0; dp < 8; dp++)
                ldsm4t(vbf[dp*2][0], vbf[dp*2][1], vbf[dp*2+1][0], vbf[dp*2+1][1],
                       vbx + (unsigned)(kr * 136 + dp * 16 + ncl) * 2);
            #pragma unroll
            for (int d = 0; d < 16; d++)
                mma16816(oacc[d], pa[kk], vbf[d]);
        }

        __syncthreads();
        if (t + 2 < 16) load_kv(t + 2, stage);
        cpa_commit();
    }

    const float i0 = 1.f / l0r, i1 = 1.f / l1r;
    __half* Og = O + ((long long)(b * S_ + s0 + r0)) * HD + h * DH;
    #pragma unroll
    for (int d = 0; d < 16; d++) {
        const int col = d * 8 + (lane & 3) * 2;
        *reinterpret_cast<__half2*>(&Og[col]) =
            __floats2half2_rn(oacc[d][0] * i0, oacc[d][1] * i0);
        *reinterpret_cast<__half2*>(&Og[(long long)8 * HD + col]) =
            __floats2half2_rn(oacc[d][2] * i1, oacc[d][3] * i1);
    }
}

// ---------------- elementwise kernels ---------------------------------------
__global__ void rope_tab_k() {
    int idx = blockIdx.x * blockDim.x + threadIdx.x;
    if (idx >= S_ * (DH/2)) return;
    int s = idx >> 6, p = idx & 63;
    float inv = powf(10000.0f, -(float)(2 * p) / (float)DH);
    float ang = (float)s * inv;
    float sn, cs; sincosf(ang, &sn, &cs);
    g_rope[idx] = make_float2(cs, sn);
}

#define SEG_BIG  (HD*HD)
#define SEG_SM   (HD*KVD)
__global__ void f2h_all_k(const float* __restrict__ wq, const float* __restrict__ wk,
                          const float* __restrict__ wv, const float* __restrict__ wo,
                          const float* __restrict__ wg, const float* __restrict__ wu,
                          const float* __restrict__ wd,
                          __half* __restrict__ wqkv, __half* __restrict__ oo,
                          __half* __restrict__ wgu, __half* __restrict__ od) {
    long long i = ((long long)blockIdx.x * blockDim.x + threadIdx.x) * 8;
    const long long big = SEG_BIG, sg = SEG_SM;
    if (i >= big + 2*sg + big && i < big + 2*sg + 2*big) {
        long long off = i - big - 2*sg - big;
        long long row = off >> 11, j = off & 2047;
        float4 gA = *reinterpret_cast<const float4*>(&wg[off]);
        float4 gB = *reinterpret_cast<const float4*>(&wg[off + 4]);
        float4 uA = *reinterpret_cast<const float4*>(&wu[off]);
        float4 uB = *reinterpret_cast<const float4*>(&wu[off + 4]);
        __half* dst = wgu + row * GUN + 2 * j;
        uint4 o0, o1;
        o0.x = packh2(gA.x, uA.x); o0.y = packh2(gA.y, uA.y);
        o0.z = packh2(gA.z, uA.z); o0.w = packh2(gA.w, uA.w);
        o1.x = packh2(gB.x, uB.x); o1.y = packh2(gB.y, uB.y);
        o1.z = packh2(gB.z, uB.z); o1.w = packh2(gB.w, uB.w);
        *reinterpret_cast<uint4*>(dst)     = o0;
        *reinterpret_cast<uint4*>(dst + 8) = o1;
        return;
    }
    const float* src; __half* dst; long long off, doff;
    if (i < big) {
        src = wq; off = i;
        doff = (off >> 11) * QKVN + (off & 2047);
        dst = wqkv;
    } else if (i < big + sg) {
        src = wk; off = i - big;
        doff = (off >> 9) * QKVN + HD + (off & 511);
        dst = wqkv;
    } else if (i < big + 2*sg) {
        src = wv; off = i - big - sg;
        doff = (off >> 9) * QKVN + HD + KVD + (off & 511);
        dst = wqkv;
    } else if (i < big + 2*sg + big) {
        src = wo; off = i - big - 2*sg; dst = oo; doff = off;
    } else {
        src = wd; off = i - big - 2*sg - 2*big; dst = od; doff = off;
    }
    float4 v0 = *reinterpret_cast<const float4*>(&src[off]);
    float4 v1 = *reinterpret_cast<const float4*>(&src[off + 4]);
    uint4 u;
    u.x = packh2(v0.x, v0.y); u.y = packh2(v0.z, v0.w);
    u.z = packh2(v1.x, v1.y); u.w = packh2(v1.z, v1.w);
    *reinterpret_cast<uint4*>(&dst[doff]) = u;
}

__global__ void bias_gu_k(const float* __restrict__ bg, const float* __restrict__ bu) {
    int j = blockIdx.x * blockDim.x + threadIdx.x;
    if (j >= HD) return;
    g_bgu[2*j]   = bg[j];
    g_bgu[2*j+1] = bu[j];
}

__global__ void rmsnorm_h(const float* __restrict__ x, const float* __restrict__ g,
                          __half* __restrict__ o) {
    __shared__ float swarp[8];
    const int row = blockIdx.x, tid = threadIdx.x;
    const int lane = tid & 31, warp = tid >> 5;
    const float* xr = x + (long long)row * HD + tid * 8;

    float4 a = *reinterpret_cast<const float4*>(xr);
    float4 b = *reinterpret_cast<const float4*>(xr + 4);
    float s = a.x*a.x + a.y*a.y + a.z*a.z + a.w*a.w
            + b.x*b.x + b.y*b.y + b.z*b.z + b.w*b.w;
    #pragma unroll
    for (int st = 16; st > 0; st >>= 1)
        s += __shfl_xor_sync(0xffffffffu, s, st);
    if (lane == 0) swarp[warp] = s;
    __syncthreads();
    if (warp == 0) {
        float t = (lane < 8) ? swarp[lane] : 0.f;
        #pragma unroll
        for (int st = 4; st > 0; st >>= 1)
            t += __shfl_xor_sync(0xffffffffu, t, st);
        if (lane == 0) swarp[0] = t;
    }
    __syncthreads();
    const float inv = rsqrtf(swarp[0] / (float)HD + 1e-8f);

    const float* gr = g + tid * 8;
    float4 ga = *reinterpret_cast<const float4*>(gr);
    float4 gb = *reinterpret_cast<const float4*>(gr + 4);
    uint4 u;
    u.x = packh2(a.x * inv * ga.x, a.y * inv * ga.y);
    u.y = packh2(a.z * inv * ga.z, a.w * inv * ga.w);
    u.z = packh2(b.x * inv * gb.x, b.y * inv * gb.y);
    u.w = packh2(b.z * inv * gb.z, b.w * inv * gb.w);
    *reinterpret_cast<uint4*>(o + (long long)row * HD + tid * 8) = u;
}

// ---------------- host side --------------------------------------------------
static const int SMEM_G  = 3 * (128 * 72 + 64 * 136) * 2;   // 107520
static const int SMEM_FA = 4096 + 2 * 2 * 8704 * 2;         // 73728

template<bool OUTH, bool SILU, bool ROPE>
static void launch_gemm(const __half* A, const __half* B,
                        float* Cf, __half* Ch,
                        const float* bias, const float* resid,
                        int M, int N, int K, int lda, int ldb, int ldc, int ldr,
                        float scale) {
    dim3 grid(N / 128, M / 128), block(256);
    cudaFuncSetAttribute(hgemm_k<OUTH, SILU, ROPE>,
                         cudaFuncAttributeMaxDynamicSharedMemorySize, SMEM_G);
    hgemm_k<OUTH, SILU, ROPE><<<grid, block, SMEM_G>>>(
        A, B, Cf, Ch, bias, resid, M, N, K, lda, ldb, ldc, ldr, scale);
}

extern "C" void kernel_launch(void* const* d_in, const int* in_sizes, int n_in,
                              void* d_out, int out_size) {
    const float* enc    = (const float*)d_in[0];
    const float* mask   = (const float*)d_in[1];
    const float* gin    = (const float*)d_in[4];
    const float* gffn   = (const float*)d_in[5];
    const float* w_q    = (const float*)d_in[6];
    const float* b_q    = (const float*)d_in[7];
    const float* w_k    = (const float*)d_in[8];
    const float* b_k    = (const float*)d_in[9];
    const float* w_v    = (const float*)d_in[10];
    const float* b_v    = (const float*)d_in[11];
    const float* w_o    = (const float*)d_in[12];
    const float* b_o    = (const float*)d_in[13];
    const float* w_gate = (const float*)d_in[14];
    const float* b_gate = (const float*)d_in[15];
    const float* w_up   = (const float*)d_in[16];
    const float* b_up   = (const float*)d_in[17];
    const float* w_down = (const float*)d_in[18];
    const float* b_down = (const float*)d_in[19];
    float* out = (float*)d_out;

    float *ao, *bqkv, *bgu;
    __half *wqkv, *woh, *wgu, *wdh;
    __half *xnh, *qkv, *cxh, *hh, *guh;
    cudaGetSymbolAddress((void**)&ao,   g_ao);
    cudaGetSymbolAddress((void**)&bqkv, g_bqkv);
    cudaGetSymbolAddress((void**)&bgu,  g_bgu);
    cudaGetSymbolAddress((void**)&wqkv, g_wqkv);
    cudaGetSymbolAddress((void**)&woh,  g_woh);
    cudaGetSymbolAddress((void**)&wgu,  g_wgu);
    cudaGetSymbolAddress((void**)&wdh,  g_wdh);
    cudaGetSymbolAddress((void**)&xnh,  g_xnh);
    cudaGetSymbolAddress((void**)&qkv,  g_qkv);
    cudaGetSymbolAddress((void**)&cxh,  g_cxh);
    cudaGetSymbolAddress((void**)&hh,   g_hh);
    cudaGetSymbolAddress((void**)&guh,  g_guh);

    // 0) rope table + weights -> fp16 (q/k/v packed, gate/up interleaved)
    rope_tab_k<<<(S_ * (DH/2)) / 256, 256>>>();
    {
        long long tot = 4LL * SEG_BIG + 2LL * SEG_SM;
        f2h_all_k<<<(unsigned)(tot / 2048), 256>>>(
            w_q, w_k, w_v, w_o, w_gate, w_up, w_down,
            wqkv, woh, wgu, wdh);
        bias_gu_k<<<HD / 256, 256>>>(b_gate, b_up);
        cudaMemcpyAsync(bqkv,            b_q, HD  * sizeof(float), cudaMemcpyDeviceToDevice);
        cudaMemcpyAsync(bqkv + HD,       b_k, KVD * sizeof(float), cudaMemcpyDeviceToDevice);
        cudaMemcpyAsync(bqkv + HD + KVD, b_v, KVD * sizeof(float), cudaMemcpyDeviceToDevice);
    }

    // 1) x = RMSNorm(enc) -> fp16
    rmsnorm_h<<<T_, 256>>>(enc, gin, xnh);

    // 2) fused QKV projection with RoPE in epilogue -> packed [T, 3072] fp16
    launch_gemm<true, false, true>(xnh, wqkv, nullptr, qkv, bqkv, nullptr,
                                   T_, QKVN, HD, HD, QKVN, QKVN, 0, 1.0f);

    // 3-6) fused flash attention -> ctx fp16 [B,S,HD]   (64-row q-tiles)
    {
        cudaFuncSetAttribute(flash_k, cudaFuncAttributeMaxDynamicSharedMemorySize, SMEM_FA);
        dim3 grid(S_ / 64, NH, B_);
        flash_k<<<grid, 128, SMEM_FA>>>(qkv, mask, cxh);
    }

    // 7) attn_out = enc + ctx @ w_o + b_o   (fp32)
    launch_gemm<false, false, false>(cxh, woh, ao, nullptr, b_o, enc,
                                     T_, HD, HD, HD, HD, HD, HD, 1.0f);

    // 8) h = RMSNorm(attn_out) -> fp16
    rmsnorm_h<<<T_, 256>>>(ao, gffn, hh);

    // 9) fused gate|up GEMM with SiLU epilogue -> guh fp16 [T, HD]
    launch_gemm<true, true, false>(hh, wgu, nullptr, guh, bgu, nullptr,
                                   T_, GUN, HD, HD, GUN, HD, 0, 1.0f);

    // 10) out = attn_out + gu @ w_down + b_down
    launch_gemm<false, false, false>(guh, wdh, out, nullptr, b_down, ao,
                                     T_, HD, HD, HD, HD, HD, HD, 1.0f);
}